// round 12
// baseline (speedup 1.0000x reference)
#include <cuda_runtime.h>
#include <cuda_fp16.h>
#include <stdint.h>
#include <math.h>

#define Bb 4
#define Ss 2048
#define Dd 1024
#define Hh 16
#define Nn 256
#define DDd 64

// ---------------- scratch (device globals; no allocation allowed) ----------
__device__ __half g_U[9216 * 1024];          // pooled GEMM A fp16 [x][d][b][t] x K
__device__ __half g_G[9216 * 1024];          // projection GEMM outputs (fp16)
__device__ __half g_Wh[4 * 1024 * 1024];     // fp16 weights [N,K]: Wq,Wk,Wv,W2
__device__ float g_pool[3 * Bb * Hh * Nn * DDd];  // [x][b][h][t][dd]
__device__ __half g_OP[1024 * 1024];         // attn output, merged layout [b*t][h*64+dd]
__device__ float g_bias2[1024];              // bc + bup_tiled @ Wc

// ---------------- PTX helpers ----------------------------------------------
static __device__ __forceinline__ uint32_t smem_u32(const void* p) {
    uint32_t r;
    asm("{ .reg .u64 t; cvta.to.shared.u64 t, %1; cvt.u32.u64 %0, t; }" : "=r"(r) : "l"(p));
    return r;
}
static __device__ __forceinline__ void cp16(uint32_t dst, const void* src) {
    asm volatile("cp.async.cg.shared.global [%0], [%1], 16;" :: "r"(dst), "l"(src));
}
#define CP_COMMIT() asm volatile("cp.async.commit_group;" ::: "memory")
#define CP_WAIT1()  asm volatile("cp.async.wait_group 1;" ::: "memory")

static __device__ __forceinline__ void ldsm_x4(uint32_t* r, uint32_t addr) {
    asm volatile("ldmatrix.sync.aligned.m8n8.x4.shared.b16 {%0,%1,%2,%3}, [%4];"
                 : "=r"(r[0]), "=r"(r[1]), "=r"(r[2]), "=r"(r[3]) : "r"(addr));
}
static __device__ __forceinline__ void mma_f16(float* c, const uint32_t* a, const uint32_t* b) {
    asm volatile(
        "mma.sync.aligned.m16n8k16.row.col.f32.f16.f16.f32 "
        "{%0,%1,%2,%3}, {%4,%5,%6,%7}, {%8,%9}, {%0,%1,%2,%3};"
        : "+f"(c[0]), "+f"(c[1]), "+f"(c[2]), "+f"(c[3])
        : "r"(a[0]), "r"(a[1]), "r"(a[2]), "r"(a[3]), "r"(b[0]), "r"(b[1]));
}

static __device__ __forceinline__ float4 f4add(float4 a, float4 b) {
    return make_float4(a.x + b.x, a.y + b.y, a.z + b.z, a.w + b.w);
}

// ---------------------------------------------------------------------------
// PREP kernel: one launch doing all independent preprocessing, dispatched on
// blockIdx.z.
//   z = 0..2 : pool for input x=z (sliding-window, 8 pooled steps/block)
//   z = 3..5 : transpose Wq/Wk/Wv [K,N]->[N,K], round fp16
//   z = 6    : W2 = blockdiag(Wup) @ Wc (fp16, transposed) + bias2
// Grid (32, 32, 7), 256 threads.
// ---------------------------------------------------------------------------
#define TSTEP 8
__global__ void __launch_bounds__(256) prep_kernel(
        const float* __restrict__ q, const float* __restrict__ k, const float* __restrict__ v,
        const float* __restrict__ Wq, const float* __restrict__ Wk, const float* __restrict__ Wv,
        const float* __restrict__ Wup, const float* __restrict__ Wc,
        const float* __restrict__ bup, const float* __restrict__ bc) {
    const int z = blockIdx.z;
    const int tid = threadIdx.x;

    if (z < 3) {
        // ---- pool: x=z, tr=blockIdx.x (0..31), b=blockIdx.y (<4) ----
        const int b = blockIdx.y;
        if (b >= Bb) return;
        const int tr = blockIdx.x;
        const float* src = (z == 0) ? q : ((z == 1) ? k : v);
        const float4* S = (const float4*)(src + (size_t)b * Ss * Dd);
        const int c4 = tid;
        const int t0 = tr * TSTEP;

        float4 zero = make_float4(0.f, 0.f, 0.f, 0.f);
        int r0 = 8 * t0 - 9, r1 = 8 * t0 - 8;
        float4 prev0 = (r0 >= 0) ? S[(size_t)r0 * 256 + c4] : zero;
        float4 prev1 = (r1 >= 0) ? S[(size_t)r1 * 256 + c4] : zero;

        #pragma unroll
        for (int t = t0; t < t0 + TSTEP; t++) {
            float4 nw[8];
            #pragma unroll
            for (int kk = 0; kk < 8; kk++) {
                int rr = 8 * t - 7 + kk;
                nw[kk] = (rr >= 0) ? S[(size_t)rr * 256 + c4] : zero;
            }
            float4 p6 = f4add(f4add(f4add(nw[0], nw[1]), f4add(nw[2], nw[3])), f4add(nw[4], nw[5]));
            float4 s0 = f4add(f4add(prev0, prev1), p6);
            float4 s1 = f4add(prev1, f4add(p6, nw[6]));
            float4 s2 = f4add(p6, f4add(nw[6], nw[7]));
            float4 sv[3] = {s0, s1, s2};
            #pragma unroll
            for (int d = 0; d < 3; d++) {
                size_t row = (((size_t)(z * 3 + d)) * Bb + b) * Nn + t;
                __half2* dst = (__half2*)g_U + row * 512 + c4 * 2;
                dst[0] = __floats2half2_rn(sv[d].x, sv[d].y);
                dst[1] = __floats2half2_rn(sv[d].z, sv[d].w);
            }
            prev0 = nw[6];
            prev1 = nw[7];
        }
    } else if (z < 6) {
        // ---- weight transpose + fp16 round ----
        const float* W = (z == 3) ? Wq : ((z == 4) ? Wk : Wv);
        __half* Oh = g_Wh + (size_t)(z - 3) * 1024 * 1024;
        __shared__ float tile[32][33];
        const int n0 = blockIdx.x * 32, k0 = blockIdx.y * 32;
        const int tx = tid & 31, ty = tid >> 5;
        #pragma unroll
        for (int j = 0; j < 4; j++)
            tile[ty + j * 8][tx] = W[(size_t)(k0 + ty + j * 8) * 1024 + n0 + tx];
        __syncthreads();
        #pragma unroll
        for (int j = 0; j < 4; j++) {
            float val = tile[tx][ty + j * 8];
            Oh[(size_t)(n0 + ty + j * 8) * 1024 + k0 + tx] = __float2half_rn(val);
        }
    } else {
        // ---- W2[r=h*64+dd, c] = sum_j Wup[dd,j] * Wc[h*64+j, c]; stored
        //      transposed fp16 at g_Wh slot 3: W2t[c*1024 + r]. Also bias2.
        const int bx = blockIdx.x;          // c tile (32 cols)
        const int by = blockIdx.y;          // r tile (32 rows)
        const int h = by >> 1, ddb = (by & 1) * 32;
        __shared__ float sWup[32][65];      // dd-local x j (padded)
        __shared__ float sWc[64][32];       // j x c-local
        for (int idx = tid; idx < 32 * 64; idx += 256) {
            int dd = idx >> 6, j = idx & 63;
            sWup[dd][j] = Wup[(size_t)(ddb + dd) * 64 + j];
        }
        for (int idx = tid; idx < 64 * 32; idx += 256) {
            int j = idx >> 5, cl = idx & 31;
            sWc[j][cl] = Wc[(size_t)(h * 64 + j) * 1024 + bx * 32 + cl];
        }
        __syncthreads();
        const int rl = tid & 31;
        const int c0 = (tid >> 5) * 4;
        float o[4] = {0.f, 0.f, 0.f, 0.f};
        #pragma unroll
        for (int j = 0; j < 64; j++) {
            float a = sWup[rl][j];
            o[0] += a * sWc[j][c0 + 0];
            o[1] += a * sWc[j][c0 + 1];
            o[2] += a * sWc[j][c0 + 2];
            o[3] += a * sWc[j][c0 + 3];
        }
        __half* W2t = g_Wh + (size_t)3 * 1024 * 1024;
        const int r = by * 32 + rl;
        #pragma unroll
        for (int i = 0; i < 4; i++)
            W2t[(size_t)(bx * 32 + c0 + i) * 1024 + r] = __float2half_rn(o[i]);
        // bias2 for this c-tile (one block row does it)
        if (by == 0 && tid < 32) {
            int c = bx * 32 + tid;
            float s = bc[c];
            for (int rr = 0; rr < 1024; rr++)
                s += bup[rr & 63] * Wc[(size_t)rr * 1024 + c];
            g_bias2[c] = s;
        }
    }
}

// ---------------------------------------------------------------------------
// HMMA fp16 GEMM (3-stage, measured-best): C = A @ B^T, fp32 accum.
// CTA tile (64*MI) x 128, K-step 32, 8 warps (4M x 2N), 80B-padded SMEM rows.
// BCAST=1: C is float* d_out; each row broadcast to 8 sequence rows.
// ---------------------------------------------------------------------------
#define BROWS 128

template <int MI, int BCAST>
__global__ void __launch_bounds__(256) gemm_tc(
        const __half* __restrict__ A,
        const __half* __restrict__ B0, const __half* __restrict__ B1,
        const __half* __restrict__ B2,
        void* __restrict__ Cv, const float* __restrict__ bias, int mblocks_per_x) {
    constexpr int CTAM = 64 * MI;
    constexpr int ASZ = CTAM * 80;
    constexpr int BSZ = BROWS * 80;
    constexpr int STAGE = ASZ + BSZ;

    extern __shared__ char dsm[];
    const uint32_t sbase = smem_u32(dsm);
    const int tid = threadIdx.x;
    const int wid = tid >> 5, lane = tid & 31;
    const int bn = blockIdx.x, bm = blockIdx.y;
    const int x = bm / mblocks_per_x;
    const __half* Bh = (x == 0) ? B0 : ((x == 1) ? B1 : B2);

    const int warpM = wid >> 1;
    const int warpN = wid & 1;
    const uint32_t aOff = (uint32_t)((warpM * 16 * MI + (lane & 15)) * 80 + (lane >> 4) * 16);
    const uint32_t bOff = (uint32_t)(ASZ +
        (warpN * 64 + ((lane >> 4) & 1) * 8 + (lane & 7)) * 80 + ((lane >> 3) & 1) * 16);

    float acc[MI][8][4];
    #pragma unroll
    for (int mi = 0; mi < MI; mi++)
        #pragma unroll
        for (int ni = 0; ni < 8; ni++)
            #pragma unroll
            for (int j = 0; j < 4; j++) acc[mi][ni][j] = 0.f;

    auto load_chunk = [&](int ch, int st) {
        const uint32_t bb = sbase + st * STAGE;
        const int kof = ch * 32;
        #pragma unroll
        for (int it = 0; it < MI; it++) {
            int idx = tid + it * 256;
            int r = idx >> 2, qq = idx & 3;
            uint32_t dst = bb + r * 80 + qq * 16;
            size_t g = (size_t)(bm * CTAM + r) * 1024 + kof + qq * 8;
            cp16(dst, A + g);
        }
        #pragma unroll
        for (int it = 0; it < 2; it++) {
            int idx = tid + it * 256;
            int r = idx >> 2, qq = idx & 3;
            uint32_t dst = bb + ASZ + r * 80 + qq * 16;
            size_t g = (size_t)(bn * BROWS + r) * 1024 + kof + qq * 8;
            cp16(dst, Bh + g);
        }
        CP_COMMIT();
    };

    load_chunk(0, 0);
    load_chunk(1, 1);

    for (int i = 0; i < 32; i++) {
        CP_WAIT1();
        __syncthreads();
        const uint32_t bb = sbase + (i % 3) * STAGE;
        #pragma unroll
        for (int kk = 0; kk < 2; kk++) {
            uint32_t ah[MI][4];
            #pragma unroll
            for (int mi = 0; mi < MI; mi++)
                ldsm_x4(ah[mi], bb + aOff + mi * 16 * 80 + kk * 32);
            #pragma unroll
            for (int p = 0; p < 4; p++) {
                uint32_t b4[4];
                ldsm_x4(b4, bb + bOff + p * 16 * 80 + kk * 32);
                #pragma unroll
                for (int mi = 0; mi < MI; mi++) {
                    mma_f16(acc[mi][2 * p],     ah[mi], b4);
                    mma_f16(acc[mi][2 * p + 1], ah[mi], b4 + 2);
                }
            }
        }
        if (i + 2 < 32) load_chunk(i + 2, (i + 2) % 3);
        else CP_COMMIT();
    }

    const int row0 = bm * CTAM + warpM * 16 * MI + (lane >> 2);
    const int col0 = bn * 128 + warpN * 64 + (lane & 3) * 2;
    #pragma unroll
    for (int mi = 0; mi < MI; mi++) {
        #pragma unroll
        for (int ni = 0; ni < 8; ni++) {
            int r = row0 + mi * 16;
            int c = col0 + ni * 8;
            if (BCAST) {
                float* C = (float*)Cv;
                float b0 = bias ? bias[c] : 0.f, b1 = bias ? bias[c + 1] : 0.f;
                float2 v0 = make_float2(acc[mi][ni][0] + b0, acc[mi][ni][1] + b1);
                float2 v1 = make_float2(acc[mi][ni][2] + b0, acc[mi][ni][3] + b1);
                int rb = r >> 8, rt = r & 255;
                float* o0 = C + ((size_t)rb * Ss + rt * 8) * 1024 + c;
                int r8 = r + 8;
                int rb2 = r8 >> 8, rt2 = r8 & 255;
                float* o1 = C + ((size_t)rb2 * Ss + rt2 * 8) * 1024 + c;
                #pragma unroll
                for (int rep = 0; rep < 8; rep++) {
                    *(float2*)(o0 + rep * 1024) = v0;
                    *(float2*)(o1 + rep * 1024) = v1;
                }
            } else {
                __half* C = (__half*)Cv;
                *(__half2*)&C[(size_t)r * 1024 + c] =
                    __floats2half2_rn(acc[mi][ni][0], acc[mi][ni][1]);
                *(__half2*)&C[(size_t)(r + 8) * 1024 + c] =
                    __floats2half2_rn(acc[mi][ni][2], acc[mi][ni][3]);
            }
        }
    }
}

// ---------------------------------------------------------------------------
// Combine: fold conv weights + biases + norm scale + /8 into pooled q/k/v.
// ---------------------------------------------------------------------------
__global__ void __launch_bounds__(256) combine_kernel(
        const float* __restrict__ wcq, const float* __restrict__ bcq, const float* __restrict__ bq,
        const float* __restrict__ wck, const float* __restrict__ bck, const float* __restrict__ bk,
        const float* __restrict__ wcv, const float* __restrict__ bcv, const float* __restrict__ bv) {
    const int t = blockIdx.x, b = blockIdx.y, x = blockIdx.z;
    const float* wc = (x == 0) ? wcq : ((x == 1) ? wck : wcv);
    const float* bc = (x == 0) ? bcq : ((x == 1) ? bck : bcv);
    const float* bd = (x == 0) ? bq  : ((x == 1) ? bk  : bv);
    const float scale = (x == 2) ? 1.0f : 0.35355339059327379f;  // 64^-0.25

    float cJ, c0, c1, c2;
    if (t == 0)      { cJ = 1.f; c0 = 0.f; c1 = 0.f; c2 = 1.f; }
    else if (t == 1) { cJ = 8.f; c0 = 7.f; c1 = 8.f; c2 = 8.f; }
    else             { cJ = 8.f; c0 = 8.f; c1 = 8.f; c2 = 8.f; }

    const size_t ds = (size_t)Bb * Nn * Dd;
    const size_t base0 = ((((size_t)x * 3 + 0) * Bb + b) * Nn + t) * Dd;

    for (int c = threadIdx.x; c < Dd; c += 256) {
        float G0 = __half2float(g_G[base0 + c]);
        float G1 = __half2float(g_G[base0 + ds + c]);
        float G2 = __half2float(g_G[base0 + 2 * ds + c]);
        float bdc = bd[c];
        float val = cJ * bc[c] + scale * (wc[c]          * (G0 + c0 * bdc) +
                                          wc[Dd + c]     * (G1 + c1 * bdc) +
                                          wc[2 * Dd + c] * (G2 + c2 * bdc));
        val *= 0.125f;
        int h = c >> 6, dd = c & 63;
        g_pool[((((size_t)x * Bb + b) * Hh + h) * Nn + t) * DDd + dd] = val;
    }
}

// ---------------------------------------------------------------------------
// Attention: grid (4 qtiles, 64 bh), 128 threads, 2 threads/query. Writes
// fp16 directly in merged layout g_OP[b*256+t][h*64+dd] for the final GEMM.
// ---------------------------------------------------------------------------
__global__ void __launch_bounds__(128) attn_kernel() {
    const int qt = blockIdx.x;
    const int bh = blockIdx.y;
    const int b = bh >> 4, h = bh & 15;
    __shared__ float sK[64][DDd];
    __shared__ float sV[64][DDd];
    const float* qp = g_pool + ((size_t)0 * Bb * Hh + bh) * Nn * DDd;
    const float* kp = g_pool + ((size_t)1 * Bb * Hh + bh) * Nn * DDd;
    const float* vp = g_pool + ((size_t)2 * Bb * Hh + bh) * Nn * DDd;
    const int tid = threadIdx.x;
    const int wid = tid >> 5;
    const int qi = qt * 64 + (tid >> 1);
    const int hf = (tid & 1) * 32;
    const int qiHiW = qt * 64 + wid * 16 + 15;

    float qreg[32];
    #pragma unroll
    for (int d = 0; d < 32; d++) qreg[d] = qp[(size_t)qi * DDd + hf + d];

    float mi = -1e30f, li = 0.f;
    float acc[32];
    #pragma unroll
    for (int d = 0; d < 32; d++) acc[d] = 0.f;

    for (int t = 0; t <= qt; t++) {
        for (int idx = tid; idx < 64 * DDd / 4; idx += 128) {
            ((float4*)&sK[0][0])[idx] = ((const float4*)(kp + (size_t)t * 64 * DDd))[idx];
            ((float4*)&sV[0][0])[idx] = ((const float4*)(vp + (size_t)t * 64 * DDd))[idx];
        }
        __syncthreads();
        int mW = qiHiW - t * 64; if (mW > 63) mW = 63;
        int mMe = qi - t * 64;   if (mMe > 63) mMe = 63;
        for (int m = 0; m <= mW; m++) {
            float d0 = 0.f, d1 = 0.f, d2 = 0.f, d3 = 0.f;
            #pragma unroll
            for (int d = 0; d < 32; d += 4) {
                d0 += qreg[d + 0] * sK[m][hf + d + 0];
                d1 += qreg[d + 1] * sK[m][hf + d + 1];
                d2 += qreg[d + 2] * sK[m][hf + d + 2];
                d3 += qreg[d + 3] * sK[m][hf + d + 3];
            }
            float half = (d0 + d1) + (d2 + d3);
            float dot = half + __shfl_xor_sync(0xffffffffu, half, 1);
            if (m <= mMe) {
                if (dot > mi) {
                    float f = __expf(mi - dot);
                    li *= f;
                    #pragma unroll
                    for (int d = 0; d < 32; d++) acc[d] *= f;
                    mi = dot;
                }
                float p = __expf(dot - mi);
                li += p;
                #pragma unroll
                for (int d = 0; d < 32; d++) acc[d] += p * sV[m][hf + d];
            }
        }
        __syncthreads();
    }

    float inv = 1.0f / li;
    __half2* outp = (__half2*)(g_OP + ((size_t)(b * Nn + qi)) * Dd + h * 64 + hf);
    #pragma unroll
    for (int d = 0; d < 32; d += 2)
        outp[d >> 1] = __floats2half2_rn(acc[d] * inv, acc[d + 1] * inv);
}

// ---------------------------------------------------------------------------
extern "C" void kernel_launch(void* const* d_in, const int* in_sizes, int n_in,
                              void* d_out, int out_size) {
    const float* q   = (const float*)d_in[0];
    const float* k   = (const float*)d_in[1];
    const float* v   = (const float*)d_in[2];
    const float* Wq  = (const float*)d_in[3];
    const float* bq  = (const float*)d_in[4];
    const float* Wk  = (const float*)d_in[5];
    const float* bk  = (const float*)d_in[6];
    const float* Wv  = (const float*)d_in[7];
    const float* bv  = (const float*)d_in[8];
    const float* Wup = (const float*)d_in[9];
    const float* bup = (const float*)d_in[10];
    const float* Wc  = (const float*)d_in[11];
    const float* bc  = (const float*)d_in[12];
    const float* wcq = (const float*)d_in[13];
    const float* bcq = (const float*)d_in[14];
    const float* wck = (const float*)d_in[15];
    const float* bck = (const float*)d_in[16];
    const float* wcv = (const float*)d_in[17];
    const float* bcv = (const float*)d_in[18];

    __half *pU, *pWh, *pOP, *pG;
    float *pBias2;
    cudaGetSymbolAddress((void**)&pU, g_U);
    cudaGetSymbolAddress((void**)&pWh, g_Wh);
    cudaGetSymbolAddress((void**)&pOP, g_OP);
    cudaGetSymbolAddress((void**)&pG, g_G);
    cudaGetSymbolAddress((void**)&pBias2, g_bias2);

    const int SM2 = 3 * (128 * 80 + 128 * 80);
    const int SM1 = 3 * (64 * 80 + 128 * 80);
    cudaFuncSetAttribute((const void*)gemm_tc<2, 0>, cudaFuncAttributeMaxDynamicSharedMemorySize, SM2);
    cudaFuncSetAttribute((const void*)gemm_tc<1, 1>, cudaFuncAttributeMaxDynamicSharedMemorySize, SM1);

    // 1. All preprocessing: pool (z<3), weight transposes (z=3..5), W2+bias2 (z=6)
    prep_kernel<<<dim3(32, 32, 7), 256>>>(q, k, v, Wq, Wk, Wv, Wup, Wc, bup, bc);

    // 2. Fused projection GEMMs: [9216,1024] @ per-x [1024,1024]^T -> fp16 G
    const size_t wstep = (size_t)1024 * 1024;
    gemm_tc<2, 0><<<dim3(8, 72), 256, SM2>>>(
        pU, pWh + 0 * wstep, pWh + 1 * wstep, pWh + 2 * wstep,
        pG, nullptr, 24);

    // 3. Combine conv weights/biases/scale -> pooled q/k/v
    combine_kernel<<<dim3(Nn, Bb, 3), 256>>>(wcq, bcq, bq, wck, bck, bk, wcv, bcv, bv);

    // 4. Causal attention (ncu capture slot) -> fp16 merged layout
    attn_kernel<<<dim3(4, Bb * Hh), 128>>>();

    // 5. Final dense with folded Wup+Wc (+bias2), broadcast epilogue to d_out
    gemm_tc<1, 1><<<dim3(8, 16), 256, SM1>>>(
        pOP, pWh + 3 * wstep, pWh + 3 * wstep, pWh + 3 * wstep,
        (void*)d_out, pBias2, 16);
}

// round 13
// speedup vs baseline: 1.1398x; 1.1398x over previous
#include <cuda_runtime.h>
#include <cuda_fp16.h>
#include <stdint.h>
#include <math.h>

#define Bb 4
#define Ss 2048
#define Dd 1024
#define Hh 16
#define Nn 256
#define DDd 64

// ---------------- scratch (device globals; no allocation allowed) ----------
__device__ __half g_U[9216 * 1024];          // pooled GEMM A fp16
__device__ __half g_G[9216 * 1024];          // projection GEMM outputs (fp16)
__device__ __half g_Wh[4 * 1024 * 1024];     // fp16 weights [N,K]: Wq,Wk,Wv,W2
__device__ float g_pool[3 * Bb * Hh * Nn * DDd];  // [x][b][h][t][dd]
__device__ __half g_OP[1024 * 1024];         // attn output, merged [b*t][h*64+dd]
__device__ float g_bias2[1024];              // bc + bup_tiled @ Wc
__device__ float g_pm[64 * 256 * 4];         // split-KV partial max
__device__ float g_pl[64 * 256 * 4];         // split-KV partial sum
__device__ float g_pacc[64 * 256 * 4 * 64];  // split-KV partial acc (unnormalized)

__device__ __constant__ int c_qt[10] = {0,1,1,2,2,2,3,3,3,3};
__device__ __constant__ int c_kc[10] = {0,0,1,0,1,2,0,1,2,3};

// ---------------- PTX helpers ----------------------------------------------
static __device__ __forceinline__ uint32_t smem_u32(const void* p) {
    uint32_t r;
    asm("{ .reg .u64 t; cvta.to.shared.u64 t, %1; cvt.u32.u64 %0, t; }" : "=r"(r) : "l"(p));
    return r;
}
static __device__ __forceinline__ void cp16(uint32_t dst, const void* src) {
    asm volatile("cp.async.cg.shared.global [%0], [%1], 16;" :: "r"(dst), "l"(src));
}
#define CP_COMMIT() asm volatile("cp.async.commit_group;" ::: "memory")
#define CP_WAIT1()  asm volatile("cp.async.wait_group 1;" ::: "memory")

static __device__ __forceinline__ void ldsm_x4(uint32_t* r, uint32_t addr) {
    asm volatile("ldmatrix.sync.aligned.m8n8.x4.shared.b16 {%0,%1,%2,%3}, [%4];"
                 : "=r"(r[0]), "=r"(r[1]), "=r"(r[2]), "=r"(r[3]) : "r"(addr));
}
static __device__ __forceinline__ void mma_f16(float* c, const uint32_t* a, const uint32_t* b) {
    asm volatile(
        "mma.sync.aligned.m16n8k16.row.col.f32.f16.f16.f32 "
        "{%0,%1,%2,%3}, {%4,%5,%6,%7}, {%8,%9}, {%0,%1,%2,%3};"
        : "+f"(c[0]), "+f"(c[1]), "+f"(c[2]), "+f"(c[3])
        : "r"(a[0]), "r"(a[1]), "r"(a[2]), "r"(a[3]), "r"(b[0]), "r"(b[1]));
}

static __device__ __forceinline__ float4 f4add(float4 a, float4 b) {
    return make_float4(a.x + b.x, a.y + b.y, a.z + b.z, a.w + b.w);
}

// ---------------------------------------------------------------------------
// PREP kernel: all independent preprocessing, dispatched on blockIdx.z.
//   z = 0..2 : pool for input x=z ; z = 3..5 : transpose W -> fp16
//   z = 6    : W2 = blockdiag(Wup) @ Wc (fp16, transposed) + bias2 (parallel)
// ---------------------------------------------------------------------------
#define TSTEP 8
__global__ void __launch_bounds__(256) prep_kernel(
        const float* __restrict__ q, const float* __restrict__ k, const float* __restrict__ v,
        const float* __restrict__ Wq, const float* __restrict__ Wk, const float* __restrict__ Wv,
        const float* __restrict__ Wup, const float* __restrict__ Wc,
        const float* __restrict__ bup, const float* __restrict__ bc) {
    const int z = blockIdx.z;
    const int tid = threadIdx.x;

    if (z < 3) {
        const int b = blockIdx.y;
        if (b >= Bb) return;
        const int tr = blockIdx.x;
        const float* src = (z == 0) ? q : ((z == 1) ? k : v);
        const float4* S = (const float4*)(src + (size_t)b * Ss * Dd);
        const int c4 = tid;
        const int t0 = tr * TSTEP;

        float4 zero = make_float4(0.f, 0.f, 0.f, 0.f);
        int r0 = 8 * t0 - 9, r1 = 8 * t0 - 8;
        float4 prev0 = (r0 >= 0) ? S[(size_t)r0 * 256 + c4] : zero;
        float4 prev1 = (r1 >= 0) ? S[(size_t)r1 * 256 + c4] : zero;

        #pragma unroll
        for (int t = t0; t < t0 + TSTEP; t++) {
            float4 nw[8];
            #pragma unroll
            for (int kk = 0; kk < 8; kk++) {
                int rr = 8 * t - 7 + kk;
                nw[kk] = (rr >= 0) ? S[(size_t)rr * 256 + c4] : zero;
            }
            float4 p6 = f4add(f4add(f4add(nw[0], nw[1]), f4add(nw[2], nw[3])), f4add(nw[4], nw[5]));
            float4 s0 = f4add(f4add(prev0, prev1), p6);
            float4 s1 = f4add(prev1, f4add(p6, nw[6]));
            float4 s2 = f4add(p6, f4add(nw[6], nw[7]));
            float4 sv[3] = {s0, s1, s2};
            #pragma unroll
            for (int d = 0; d < 3; d++) {
                size_t row = (((size_t)(z * 3 + d)) * Bb + b) * Nn + t;
                __half2* dst = (__half2*)g_U + row * 512 + c4 * 2;
                dst[0] = __floats2half2_rn(sv[d].x, sv[d].y);
                dst[1] = __floats2half2_rn(sv[d].z, sv[d].w);
            }
            prev0 = nw[6];
            prev1 = nw[7];
        }
    } else if (z < 6) {
        const float* W = (z == 3) ? Wq : ((z == 4) ? Wk : Wv);
        __half* Oh = g_Wh + (size_t)(z - 3) * 1024 * 1024;
        __shared__ float tile[32][33];
        const int n0 = blockIdx.x * 32, k0 = blockIdx.y * 32;
        const int tx = tid & 31, ty = tid >> 5;
        #pragma unroll
        for (int j = 0; j < 4; j++)
            tile[ty + j * 8][tx] = W[(size_t)(k0 + ty + j * 8) * 1024 + n0 + tx];
        __syncthreads();
        #pragma unroll
        for (int j = 0; j < 4; j++) {
            float val = tile[tx][ty + j * 8];
            Oh[(size_t)(n0 + ty + j * 8) * 1024 + k0 + tx] = __float2half_rn(val);
        }
    } else {
        // W2[r=h*64+dd, c] = sum_j Wup[dd,j] * Wc[h*64+j, c], stored transposed.
        const int bx = blockIdx.x;          // c tile (32 cols)
        const int by = blockIdx.y;          // r tile (32 rows)
        const int h = by >> 1, ddb = (by & 1) * 32;
        __shared__ float sWup[32][65];
        __shared__ float sWc[64][32];
        for (int idx = tid; idx < 32 * 64; idx += 256) {
            int dd = idx >> 6, j = idx & 63;
            sWup[dd][j] = Wup[(size_t)(ddb + dd) * 64 + j];
        }
        for (int idx = tid; idx < 64 * 32; idx += 256) {
            int j = idx >> 5, cl = idx & 31;
            sWc[j][cl] = Wc[(size_t)(h * 64 + j) * 1024 + bx * 32 + cl];
        }
        __syncthreads();
        const int rl = tid & 31;
        const int c0 = (tid >> 5) * 4;
        float o[4] = {0.f, 0.f, 0.f, 0.f};
        #pragma unroll
        for (int j = 0; j < 64; j++) {
            float a = sWup[rl][j];
            o[0] += a * sWc[j][c0 + 0];
            o[1] += a * sWc[j][c0 + 1];
            o[2] += a * sWc[j][c0 + 2];
            o[3] += a * sWc[j][c0 + 3];
        }
        __half* W2t = g_Wh + (size_t)3 * 1024 * 1024;
        const int r = by * 32 + rl;
        #pragma unroll
        for (int i = 0; i < 4; i++)
            W2t[(size_t)(bx * 32 + c0 + i) * 1024 + r] = __float2half_rn(o[i]);
        // bias2, parallel: 8 threads per column, 128 rows each
        if (by == 0) {
            __shared__ float red[32][9];
            int col = tid >> 3, part = tid & 7;
            int c = bx * 32 + col;
            float s = 0.f;
            for (int rr = part * 128; rr < part * 128 + 128; rr++)
                s += bup[rr & 63] * Wc[(size_t)rr * 1024 + c];
            red[col][part] = s;
            __syncthreads();
            if (part == 0) {
                float tot = bc[c];
                #pragma unroll
                for (int i = 0; i < 8; i++) tot += red[col][i];
                g_bias2[c] = tot;
            }
        }
    }
}

// ---------------------------------------------------------------------------
// HMMA fp16 GEMM (3-stage, measured-best): C = A @ B^T, fp32 accum.
// ---------------------------------------------------------------------------
#define BROWS 128

template <int MI, int BCAST>
__global__ void __launch_bounds__(256) gemm_tc(
        const __half* __restrict__ A,
        const __half* __restrict__ B0, const __half* __restrict__ B1,
        const __half* __restrict__ B2,
        void* __restrict__ Cv, const float* __restrict__ bias, int mblocks_per_x) {
    constexpr int CTAM = 64 * MI;
    constexpr int ASZ = CTAM * 80;
    constexpr int BSZ = BROWS * 80;
    constexpr int STAGE = ASZ + BSZ;

    extern __shared__ char dsm[];
    const uint32_t sbase = smem_u32(dsm);
    const int tid = threadIdx.x;
    const int wid = tid >> 5, lane = tid & 31;
    const int bn = blockIdx.x, bm = blockIdx.y;
    const int x = bm / mblocks_per_x;
    const __half* Bh = (x == 0) ? B0 : ((x == 1) ? B1 : B2);

    const int warpM = wid >> 1;
    const int warpN = wid & 1;
    const uint32_t aOff = (uint32_t)((warpM * 16 * MI + (lane & 15)) * 80 + (lane >> 4) * 16);
    const uint32_t bOff = (uint32_t)(ASZ +
        (warpN * 64 + ((lane >> 4) & 1) * 8 + (lane & 7)) * 80 + ((lane >> 3) & 1) * 16);

    float acc[MI][8][4];
    #pragma unroll
    for (int mi = 0; mi < MI; mi++)
        #pragma unroll
        for (int ni = 0; ni < 8; ni++)
            #pragma unroll
            for (int j = 0; j < 4; j++) acc[mi][ni][j] = 0.f;

    auto load_chunk = [&](int ch, int st) {
        const uint32_t bb = sbase + st * STAGE;
        const int kof = ch * 32;
        #pragma unroll
        for (int it = 0; it < MI; it++) {
            int idx = tid + it * 256;
            int r = idx >> 2, qq = idx & 3;
            uint32_t dst = bb + r * 80 + qq * 16;
            size_t g = (size_t)(bm * CTAM + r) * 1024 + kof + qq * 8;
            cp16(dst, A + g);
        }
        #pragma unroll
        for (int it = 0; it < 2; it++) {
            int idx = tid + it * 256;
            int r = idx >> 2, qq = idx & 3;
            uint32_t dst = bb + ASZ + r * 80 + qq * 16;
            size_t g = (size_t)(bn * BROWS + r) * 1024 + kof + qq * 8;
            cp16(dst, Bh + g);
        }
        CP_COMMIT();
    };

    load_chunk(0, 0);
    load_chunk(1, 1);

    for (int i = 0; i < 32; i++) {
        CP_WAIT1();
        __syncthreads();
        const uint32_t bb = sbase + (i % 3) * STAGE;
        #pragma unroll
        for (int kk = 0; kk < 2; kk++) {
            uint32_t ah[MI][4];
            #pragma unroll
            for (int mi = 0; mi < MI; mi++)
                ldsm_x4(ah[mi], bb + aOff + mi * 16 * 80 + kk * 32);
            #pragma unroll
            for (int p = 0; p < 4; p++) {
                uint32_t b4[4];
                ldsm_x4(b4, bb + bOff + p * 16 * 80 + kk * 32);
                #pragma unroll
                for (int mi = 0; mi < MI; mi++) {
                    mma_f16(acc[mi][2 * p],     ah[mi], b4);
                    mma_f16(acc[mi][2 * p + 1], ah[mi], b4 + 2);
                }
            }
        }
        if (i + 2 < 32) load_chunk(i + 2, (i + 2) % 3);
        else CP_COMMIT();
    }

    const int row0 = bm * CTAM + warpM * 16 * MI + (lane >> 2);
    const int col0 = bn * 128 + warpN * 64 + (lane & 3) * 2;
    #pragma unroll
    for (int mi = 0; mi < MI; mi++) {
        #pragma unroll
        for (int ni = 0; ni < 8; ni++) {
            int r = row0 + mi * 16;
            int c = col0 + ni * 8;
            if (BCAST) {
                float* C = (float*)Cv;
                float b0 = bias ? bias[c] : 0.f, b1 = bias ? bias[c + 1] : 0.f;
                float2 v0 = make_float2(acc[mi][ni][0] + b0, acc[mi][ni][1] + b1);
                float2 v1 = make_float2(acc[mi][ni][2] + b0, acc[mi][ni][3] + b1);
                int rb = r >> 8, rt = r & 255;
                float* o0 = C + ((size_t)rb * Ss + rt * 8) * 1024 + c;
                int r8 = r + 8;
                int rb2 = r8 >> 8, rt2 = r8 & 255;
                float* o1 = C + ((size_t)rb2 * Ss + rt2 * 8) * 1024 + c;
                #pragma unroll
                for (int rep = 0; rep < 8; rep++) {
                    *(float2*)(o0 + rep * 1024) = v0;
                    *(float2*)(o1 + rep * 1024) = v1;
                }
            } else {
                __half* C = (__half*)Cv;
                *(__half2*)&C[(size_t)r * 1024 + c] =
                    __floats2half2_rn(acc[mi][ni][0], acc[mi][ni][1]);
                *(__half2*)&C[(size_t)(r + 8) * 1024 + c] =
                    __floats2half2_rn(acc[mi][ni][2], acc[mi][ni][3]);
            }
        }
    }
}

// ---------------------------------------------------------------------------
// Combine: fold conv weights + biases + norm scale + /8 into pooled q/k/v.
// ---------------------------------------------------------------------------
__global__ void __launch_bounds__(256) combine_kernel(
        const float* __restrict__ wcq, const float* __restrict__ bcq, const float* __restrict__ bq,
        const float* __restrict__ wck, const float* __restrict__ bck, const float* __restrict__ bk,
        const float* __restrict__ wcv, const float* __restrict__ bcv, const float* __restrict__ bv) {
    const int t = blockIdx.x, b = blockIdx.y, x = blockIdx.z;
    const float* wc = (x == 0) ? wcq : ((x == 1) ? wck : wcv);
    const float* bc = (x == 0) ? bcq : ((x == 1) ? bck : bcv);
    const float* bd = (x == 0) ? bq  : ((x == 1) ? bk  : bv);
    const float scale = (x == 2) ? 1.0f : 0.35355339059327379f;

    float cJ, c0, c1, c2;
    if (t == 0)      { cJ = 1.f; c0 = 0.f; c1 = 0.f; c2 = 1.f; }
    else if (t == 1) { cJ = 8.f; c0 = 7.f; c1 = 8.f; c2 = 8.f; }
    else             { cJ = 8.f; c0 = 8.f; c1 = 8.f; c2 = 8.f; }

    const size_t ds = (size_t)Bb * Nn * Dd;
    const size_t base0 = ((((size_t)x * 3 + 0) * Bb + b) * Nn + t) * Dd;

    for (int c = threadIdx.x; c < Dd; c += 256) {
        float G0 = __half2float(g_G[base0 + c]);
        float G1 = __half2float(g_G[base0 + ds + c]);
        float G2 = __half2float(g_G[base0 + 2 * ds + c]);
        float bdc = bd[c];
        float val = cJ * bc[c] + scale * (wc[c]          * (G0 + c0 * bdc) +
                                          wc[Dd + c]     * (G1 + c1 * bdc) +
                                          wc[2 * Dd + c] * (G2 + c2 * bdc));
        val *= 0.125f;
        int h = c >> 6, dd = c & 63;
        g_pool[((((size_t)x * Bb + b) * Hh + h) * Nn + t) * DDd + dd] = val;
    }
}

// ---------------------------------------------------------------------------
// Attention partial (split-KV): grid (10 tile-pairs, 64 bh), 128 threads.
// Pair p -> (qt, kc); block processes queries qt*64.. over key tile kc.
// 2 threads/query; online softmax within the 64-key tile; writes
// unnormalized partials (m, l, acc) to global scratch.
// ---------------------------------------------------------------------------
__global__ void __launch_bounds__(128) attn_partial() {
    const int qt = c_qt[blockIdx.x];
    const int kc = c_kc[blockIdx.x];
    const int bh = blockIdx.y;
    __shared__ float sK[64][DDd];
    __shared__ float sV[64][DDd];
    const float* qp = g_pool + ((size_t)0 * Bb * Hh + bh) * Nn * DDd;
    const float* kp = g_pool + ((size_t)1 * Bb * Hh + bh) * Nn * DDd;
    const float* vp = g_pool + ((size_t)2 * Bb * Hh + bh) * Nn * DDd;
    const int tid = threadIdx.x;
    const int wid = tid >> 5;
    const int qi = qt * 64 + (tid >> 1);
    const int hf = (tid & 1) * 32;
    const int qiHiW = qt * 64 + wid * 16 + 15;

    for (int idx = tid; idx < 64 * DDd / 4; idx += 128) {
        ((float4*)&sK[0][0])[idx] = ((const float4*)(kp + (size_t)kc * 64 * DDd))[idx];
        ((float4*)&sV[0][0])[idx] = ((const float4*)(vp + (size_t)kc * 64 * DDd))[idx];
    }

    float qreg[32];
    #pragma unroll
    for (int d = 0; d < 32; d++) qreg[d] = qp[(size_t)qi * DDd + hf + d];

    float mi = -1e30f, li = 0.f;
    float acc[32];
    #pragma unroll
    for (int d = 0; d < 32; d++) acc[d] = 0.f;

    __syncthreads();
    int mW = qiHiW - kc * 64; if (mW > 63) mW = 63;   // warp-uniform
    int mMe = qi - kc * 64;   if (mMe > 63) mMe = 63; // per-query causal bound
    for (int m = 0; m <= mW; m++) {
        float d0 = 0.f, d1 = 0.f, d2 = 0.f, d3 = 0.f;
        #pragma unroll
        for (int d = 0; d < 32; d += 4) {
            d0 += qreg[d + 0] * sK[m][hf + d + 0];
            d1 += qreg[d + 1] * sK[m][hf + d + 1];
            d2 += qreg[d + 2] * sK[m][hf + d + 2];
            d3 += qreg[d + 3] * sK[m][hf + d + 3];
        }
        float half = (d0 + d1) + (d2 + d3);
        float dot = half + __shfl_xor_sync(0xffffffffu, half, 1);
        if (m <= mMe) {
            if (dot > mi) {
                float f = __expf(mi - dot);
                li *= f;
                #pragma unroll
                for (int d = 0; d < 32; d++) acc[d] *= f;
                mi = dot;
            }
            float p = __expf(dot - mi);
            li += p;
            #pragma unroll
            for (int d = 0; d < 32; d++) acc[d] += p * sV[m][hf + d];
        }
    }

    const size_t pb = ((size_t)bh * Nn + qi) * 4 + kc;
    if (hf == 0) { g_pm[pb] = mi; g_pl[pb] = li; }
    float* pa = g_pacc + pb * 64 + hf;
    #pragma unroll
    for (int d = 0; d < 32; d++) pa[d] = acc[d];
}

// ---------------------------------------------------------------------------
// Attention reduce: merge <=4 partials per query, write fp16 merged layout.
// Grid (4, 64), 128 threads, 2 threads/query.
// ---------------------------------------------------------------------------
__global__ void __launch_bounds__(128) attn_reduce() {
    const int qt = blockIdx.x;
    const int bh = blockIdx.y;
    const int b = bh >> 4, h = bh & 15;
    const int tid = threadIdx.x;
    const int qi = qt * 64 + (tid >> 1);
    const int hf = (tid & 1) * 32;
    const int np = qt + 1;

    const size_t base = ((size_t)bh * Nn + qi) * 4;
    float M = -1e30f;
    for (int kk = 0; kk < np; kk++) {
        float m = g_pm[base + kk];
        if (m > M) M = m;
    }
    float w[4], L = 0.f;
    for (int kk = 0; kk < np; kk++) {
        w[kk] = __expf(g_pm[base + kk] - M);
        L += g_pl[base + kk] * w[kk];
    }
    float out[32];
    #pragma unroll
    for (int d = 0; d < 32; d++) out[d] = 0.f;
    for (int kk = 0; kk < np; kk++) {
        const float* pa = g_pacc + (base + kk) * 64 + hf;
        float ww = w[kk];
        #pragma unroll
        for (int d = 0; d < 32; d++) out[d] += ww * pa[d];
    }
    float inv = 1.0f / L;
    __half2* outp = (__half2*)(g_OP + ((size_t)(b * Nn + qi)) * Dd + h * 64 + hf);
    #pragma unroll
    for (int d = 0; d < 32; d += 2)
        outp[d >> 1] = __floats2half2_rn(out[d] * inv, out[d + 1] * inv);
}

// ---------------------------------------------------------------------------
extern "C" void kernel_launch(void* const* d_in, const int* in_sizes, int n_in,
                              void* d_out, int out_size) {
    const float* q   = (const float*)d_in[0];
    const float* k   = (const float*)d_in[1];
    const float* v   = (const float*)d_in[2];
    const float* Wq  = (const float*)d_in[3];
    const float* bq  = (const float*)d_in[4];
    const float* Wk  = (const float*)d_in[5];
    const float* bk  = (const float*)d_in[6];
    const float* Wv  = (const float*)d_in[7];
    const float* bv  = (const float*)d_in[8];
    const float* Wup = (const float*)d_in[9];
    const float* bup = (const float*)d_in[10];
    const float* Wc  = (const float*)d_in[11];
    const float* bc  = (const float*)d_in[12];
    const float* wcq = (const float*)d_in[13];
    const float* bcq = (const float*)d_in[14];
    const float* wck = (const float*)d_in[15];
    const float* bck = (const float*)d_in[16];
    const float* wcv = (const float*)d_in[17];
    const float* bcv = (const float*)d_in[18];

    __half *pU, *pWh, *pOP, *pG;
    float *pBias2;
    cudaGetSymbolAddress((void**)&pU, g_U);
    cudaGetSymbolAddress((void**)&pWh, g_Wh);
    cudaGetSymbolAddress((void**)&pOP, g_OP);
    cudaGetSymbolAddress((void**)&pG, g_G);
    cudaGetSymbolAddress((void**)&pBias2, g_bias2);

    const int SM2 = 3 * (128 * 80 + 128 * 80);
    const int SM1 = 3 * (64 * 80 + 128 * 80);
    cudaFuncSetAttribute((const void*)gemm_tc<2, 0>, cudaFuncAttributeMaxDynamicSharedMemorySize, SM2);
    cudaFuncSetAttribute((const void*)gemm_tc<1, 1>, cudaFuncAttributeMaxDynamicSharedMemorySize, SM1);

    // 1. All preprocessing: pool (z<3), weight transposes (z=3..5), W2+bias2 (z=6)
    prep_kernel<<<dim3(32, 32, 7), 256>>>(q, k, v, Wq, Wk, Wv, Wup, Wc, bup, bc);

    // 2. Fused projection GEMMs
    const size_t wstep = (size_t)1024 * 1024;
    gemm_tc<2, 0><<<dim3(8, 72), 256, SM2>>>(
        pU, pWh + 0 * wstep, pWh + 1 * wstep, pWh + 2 * wstep,
        pG, nullptr, 24);

    // 3. Combine conv weights/biases/scale -> pooled q/k/v
    combine_kernel<<<dim3(Nn, Bb, 3), 256>>>(wcq, bcq, bq, wck, bck, bk, wcv, bcv, bv);

    // 4. Attention partials (split-KV, ncu capture slot)
    attn_partial<<<dim3(10, Bb * Hh), 128>>>();

    // 5. Merge partials -> fp16 merged layout
    attn_reduce<<<dim3(4, Bb * Hh), 128>>>();

    // 6. Final dense with folded Wup+Wc (+bias2), broadcast epilogue to d_out
    gemm_tc<1, 1><<<dim3(8, 16), 256, SM1>>>(
        pOP, pWh + 3 * wstep, pWh + 3 * wstep, pWh + 3 * wstep,
        (void*)d_out, pBias2, 16);
}

// round 14
// speedup vs baseline: 1.1683x; 1.0251x over previous
#include <cuda_runtime.h>
#include <cuda_fp16.h>
#include <stdint.h>
#include <math.h>

#define Bb 4
#define Ss 2048
#define Dd 1024
#define Hh 16
#define Nn 256
#define DDd 64

// ---------------- scratch (device globals; no allocation allowed) ----------
__device__ __half g_U[9216 * 1024];          // pooled GEMM A fp16
__device__ __half g_G[9216 * 1024];          // projection GEMM outputs (fp16)
__device__ __half g_Wh[4 * 1024 * 1024];     // fp16 weights [N,K]: Wq,Wk,Wv,W2
__device__ float g_pool[3 * Bb * Hh * Nn * DDd];  // [x][b][h][t][dd]
__device__ __half g_OP[1024 * 1024];         // attn output, merged [b*t][h*64+dd]
__device__ float g_bias2[1024];              // bc + bup_tiled @ Wc
__device__ float g_pm[64 * 256 * 4];         // split-KV partial max
__device__ float g_pl[64 * 256 * 4];         // split-KV partial sum
__device__ float g_pacc[64 * 256 * 4 * 64];  // split-KV partial acc (unnormalized)

__device__ __constant__ int c_qt[10] = {0,1,1,2,2,2,3,3,3,3};
__device__ __constant__ int c_kc[10] = {0,0,1,0,1,2,0,1,2,3};

// ---------------- PTX helpers ----------------------------------------------
static __device__ __forceinline__ uint32_t smem_u32(const void* p) {
    uint32_t r;
    asm("{ .reg .u64 t; cvta.to.shared.u64 t, %1; cvt.u32.u64 %0, t; }" : "=r"(r) : "l"(p));
    return r;
}
static __device__ __forceinline__ void cp16(uint32_t dst, const void* src) {
    asm volatile("cp.async.cg.shared.global [%0], [%1], 16;" :: "r"(dst), "l"(src));
}
#define CP_COMMIT() asm volatile("cp.async.commit_group;" ::: "memory")
#define CP_WAIT1()  asm volatile("cp.async.wait_group 1;" ::: "memory")

static __device__ __forceinline__ void ldsm_x4(uint32_t* r, uint32_t addr) {
    asm volatile("ldmatrix.sync.aligned.m8n8.x4.shared.b16 {%0,%1,%2,%3}, [%4];"
                 : "=r"(r[0]), "=r"(r[1]), "=r"(r[2]), "=r"(r[3]) : "r"(addr));
}
static __device__ __forceinline__ void mma_f16(float* c, const uint32_t* a, const uint32_t* b) {
    asm volatile(
        "mma.sync.aligned.m16n8k16.row.col.f32.f16.f16.f32 "
        "{%0,%1,%2,%3}, {%4,%5,%6,%7}, {%8,%9}, {%0,%1,%2,%3};"
        : "+f"(c[0]), "+f"(c[1]), "+f"(c[2]), "+f"(c[3])
        : "r"(a[0]), "r"(a[1]), "r"(a[2]), "r"(a[3]), "r"(b[0]), "r"(b[1]));
}

static __device__ __forceinline__ float4 f4add(float4 a, float4 b) {
    return make_float4(a.x + b.x, a.y + b.y, a.z + b.z, a.w + b.w);
}

// ---------------------------------------------------------------------------
// PREP kernel: all independent preprocessing, dispatched on blockIdx.z.
// ---------------------------------------------------------------------------
#define TSTEP 8
__global__ void __launch_bounds__(256) prep_kernel(
        const float* __restrict__ q, const float* __restrict__ k, const float* __restrict__ v,
        const float* __restrict__ Wq, const float* __restrict__ Wk, const float* __restrict__ Wv,
        const float* __restrict__ Wup, const float* __restrict__ Wc,
        const float* __restrict__ bup, const float* __restrict__ bc) {
    const int z = blockIdx.z;
    const int tid = threadIdx.x;

    if (z < 3) {
        const int b = blockIdx.y;
        if (b >= Bb) return;
        const int tr = blockIdx.x;
        const float* src = (z == 0) ? q : ((z == 1) ? k : v);
        const float4* S = (const float4*)(src + (size_t)b * Ss * Dd);
        const int c4 = tid;
        const int t0 = tr * TSTEP;

        float4 zero = make_float4(0.f, 0.f, 0.f, 0.f);
        int r0 = 8 * t0 - 9, r1 = 8 * t0 - 8;
        float4 prev0 = (r0 >= 0) ? S[(size_t)r0 * 256 + c4] : zero;
        float4 prev1 = (r1 >= 0) ? S[(size_t)r1 * 256 + c4] : zero;

        #pragma unroll
        for (int t = t0; t < t0 + TSTEP; t++) {
            float4 nw[8];
            #pragma unroll
            for (int kk = 0; kk < 8; kk++) {
                int rr = 8 * t - 7 + kk;
                nw[kk] = (rr >= 0) ? S[(size_t)rr * 256 + c4] : zero;
            }
            float4 p6 = f4add(f4add(f4add(nw[0], nw[1]), f4add(nw[2], nw[3])), f4add(nw[4], nw[5]));
            float4 s0 = f4add(f4add(prev0, prev1), p6);
            float4 s1 = f4add(prev1, f4add(p6, nw[6]));
            float4 s2 = f4add(p6, f4add(nw[6], nw[7]));
            float4 sv[3] = {s0, s1, s2};
            #pragma unroll
            for (int d = 0; d < 3; d++) {
                size_t row = (((size_t)(z * 3 + d)) * Bb + b) * Nn + t;
                __half2* dst = (__half2*)g_U + row * 512 + c4 * 2;
                dst[0] = __floats2half2_rn(sv[d].x, sv[d].y);
                dst[1] = __floats2half2_rn(sv[d].z, sv[d].w);
            }
            prev0 = nw[6];
            prev1 = nw[7];
        }
    } else if (z < 6) {
        const float* W = (z == 3) ? Wq : ((z == 4) ? Wk : Wv);
        __half* Oh = g_Wh + (size_t)(z - 3) * 1024 * 1024;
        __shared__ float tile[32][33];
        const int n0 = blockIdx.x * 32, k0 = blockIdx.y * 32;
        const int tx = tid & 31, ty = tid >> 5;
        #pragma unroll
        for (int j = 0; j < 4; j++)
            tile[ty + j * 8][tx] = W[(size_t)(k0 + ty + j * 8) * 1024 + n0 + tx];
        __syncthreads();
        #pragma unroll
        for (int j = 0; j < 4; j++) {
            float val = tile[tx][ty + j * 8];
            Oh[(size_t)(n0 + ty + j * 8) * 1024 + k0 + tx] = __float2half_rn(val);
        }
    } else {
        const int bx = blockIdx.x;
        const int by = blockIdx.y;
        const int h = by >> 1, ddb = (by & 1) * 32;
        __shared__ float sWup[32][65];
        __shared__ float sWc[64][32];
        for (int idx = tid; idx < 32 * 64; idx += 256) {
            int dd = idx >> 6, j = idx & 63;
            sWup[dd][j] = Wup[(size_t)(ddb + dd) * 64 + j];
        }
        for (int idx = tid; idx < 64 * 32; idx += 256) {
            int j = idx >> 5, cl = idx & 31;
            sWc[j][cl] = Wc[(size_t)(h * 64 + j) * 1024 + bx * 32 + cl];
        }
        __syncthreads();
        const int rl = tid & 31;
        const int c0 = (tid >> 5) * 4;
        float o[4] = {0.f, 0.f, 0.f, 0.f};
        #pragma unroll
        for (int j = 0; j < 64; j++) {
            float a = sWup[rl][j];
            o[0] += a * sWc[j][c0 + 0];
            o[1] += a * sWc[j][c0 + 1];
            o[2] += a * sWc[j][c0 + 2];
            o[3] += a * sWc[j][c0 + 3];
        }
        __half* W2t = g_Wh + (size_t)3 * 1024 * 1024;
        const int r = by * 32 + rl;
        #pragma unroll
        for (int i = 0; i < 4; i++)
            W2t[(size_t)(bx * 32 + c0 + i) * 1024 + r] = __float2half_rn(o[i]);
        if (by == 0) {
            __shared__ float red[32][9];
            int col = tid >> 3, part = tid & 7;
            int c = bx * 32 + col;
            float s = 0.f;
            for (int rr = part * 128; rr < part * 128 + 128; rr++)
                s += bup[rr & 63] * Wc[(size_t)rr * 1024 + c];
            red[col][part] = s;
            __syncthreads();
            if (part == 0) {
                float tot = bc[c];
                #pragma unroll
                for (int i = 0; i < 8; i++) tot += red[col][i];
                g_bias2[c] = tot;
            }
        }
    }
}

// ---------------------------------------------------------------------------
// HMMA fp16 GEMM (3-stage, measured-best): C = A @ B^T, fp32 accum.
// ---------------------------------------------------------------------------
#define BROWS 128

template <int MI, int BCAST>
__global__ void __launch_bounds__(256) gemm_tc(
        const __half* __restrict__ A,
        const __half* __restrict__ B0, const __half* __restrict__ B1,
        const __half* __restrict__ B2,
        void* __restrict__ Cv, const float* __restrict__ bias, int mblocks_per_x) {
    constexpr int CTAM = 64 * MI;
    constexpr int ASZ = CTAM * 80;
    constexpr int BSZ = BROWS * 80;
    constexpr int STAGE = ASZ + BSZ;

    extern __shared__ char dsm[];
    const uint32_t sbase = smem_u32(dsm);
    const int tid = threadIdx.x;
    const int wid = tid >> 5, lane = tid & 31;
    const int bn = blockIdx.x, bm = blockIdx.y;
    const int x = bm / mblocks_per_x;
    const __half* Bh = (x == 0) ? B0 : ((x == 1) ? B1 : B2);

    const int warpM = wid >> 1;
    const int warpN = wid & 1;
    const uint32_t aOff = (uint32_t)((warpM * 16 * MI + (lane & 15)) * 80 + (lane >> 4) * 16);
    const uint32_t bOff = (uint32_t)(ASZ +
        (warpN * 64 + ((lane >> 4) & 1) * 8 + (lane & 7)) * 80 + ((lane >> 3) & 1) * 16);

    float acc[MI][8][4];
    #pragma unroll
    for (int mi = 0; mi < MI; mi++)
        #pragma unroll
        for (int ni = 0; ni < 8; ni++)
            #pragma unroll
            for (int j = 0; j < 4; j++) acc[mi][ni][j] = 0.f;

    auto load_chunk = [&](int ch, int st) {
        const uint32_t bb = sbase + st * STAGE;
        const int kof = ch * 32;
        #pragma unroll
        for (int it = 0; it < MI; it++) {
            int idx = tid + it * 256;
            int r = idx >> 2, qq = idx & 3;
            uint32_t dst = bb + r * 80 + qq * 16;
            size_t g = (size_t)(bm * CTAM + r) * 1024 + kof + qq * 8;
            cp16(dst, A + g);
        }
        #pragma unroll
        for (int it = 0; it < 2; it++) {
            int idx = tid + it * 256;
            int r = idx >> 2, qq = idx & 3;
            uint32_t dst = bb + ASZ + r * 80 + qq * 16;
            size_t g = (size_t)(bn * BROWS + r) * 1024 + kof + qq * 8;
            cp16(dst, Bh + g);
        }
        CP_COMMIT();
    };

    load_chunk(0, 0);
    load_chunk(1, 1);

    for (int i = 0; i < 32; i++) {
        CP_WAIT1();
        __syncthreads();
        const uint32_t bb = sbase + (i % 3) * STAGE;
        #pragma unroll
        for (int kk = 0; kk < 2; kk++) {
            uint32_t ah[MI][4];
            #pragma unroll
            for (int mi = 0; mi < MI; mi++)
                ldsm_x4(ah[mi], bb + aOff + mi * 16 * 80 + kk * 32);
            #pragma unroll
            for (int p = 0; p < 4; p++) {
                uint32_t b4[4];
                ldsm_x4(b4, bb + bOff + p * 16 * 80 + kk * 32);
                #pragma unroll
                for (int mi = 0; mi < MI; mi++) {
                    mma_f16(acc[mi][2 * p],     ah[mi], b4);
                    mma_f16(acc[mi][2 * p + 1], ah[mi], b4 + 2);
                }
            }
        }
        if (i + 2 < 32) load_chunk(i + 2, (i + 2) % 3);
        else CP_COMMIT();
    }

    const int row0 = bm * CTAM + warpM * 16 * MI + (lane >> 2);
    const int col0 = bn * 128 + warpN * 64 + (lane & 3) * 2;
    #pragma unroll
    for (int mi = 0; mi < MI; mi++) {
        #pragma unroll
        for (int ni = 0; ni < 8; ni++) {
            int r = row0 + mi * 16;
            int c = col0 + ni * 8;
            if (BCAST) {
                float* C = (float*)Cv;
                float b0 = bias ? bias[c] : 0.f, b1 = bias ? bias[c + 1] : 0.f;
                float2 v0 = make_float2(acc[mi][ni][0] + b0, acc[mi][ni][1] + b1);
                float2 v1 = make_float2(acc[mi][ni][2] + b0, acc[mi][ni][3] + b1);
                int rb = r >> 8, rt = r & 255;
                float* o0 = C + ((size_t)rb * Ss + rt * 8) * 1024 + c;
                int r8 = r + 8;
                int rb2 = r8 >> 8, rt2 = r8 & 255;
                float* o1 = C + ((size_t)rb2 * Ss + rt2 * 8) * 1024 + c;
                #pragma unroll
                for (int rep = 0; rep < 8; rep++) {
                    *(float2*)(o0 + rep * 1024) = v0;
                    *(float2*)(o1 + rep * 1024) = v1;
                }
            } else {
                __half* C = (__half*)Cv;
                *(__half2*)&C[(size_t)r * 1024 + c] =
                    __floats2half2_rn(acc[mi][ni][0], acc[mi][ni][1]);
                *(__half2*)&C[(size_t)(r + 8) * 1024 + c] =
                    __floats2half2_rn(acc[mi][ni][2], acc[mi][ni][3]);
            }
        }
    }
}

// ---------------------------------------------------------------------------
// Combine: fold conv weights + biases + norm scale + /8 into pooled q/k/v.
// ---------------------------------------------------------------------------
__global__ void __launch_bounds__(256) combine_kernel(
        const float* __restrict__ wcq, const float* __restrict__ bcq, const float* __restrict__ bq,
        const float* __restrict__ wck, const float* __restrict__ bck, const float* __restrict__ bk,
        const float* __restrict__ wcv, const float* __restrict__ bcv, const float* __restrict__ bv) {
    const int t = blockIdx.x, b = blockIdx.y, x = blockIdx.z;
    const float* wc = (x == 0) ? wcq : ((x == 1) ? wck : wcv);
    const float* bc = (x == 0) ? bcq : ((x == 1) ? bck : bcv);
    const float* bd = (x == 0) ? bq  : ((x == 1) ? bk  : bv);
    const float scale = (x == 2) ? 1.0f : 0.35355339059327379f;

    float cJ, c0, c1, c2;
    if (t == 0)      { cJ = 1.f; c0 = 0.f; c1 = 0.f; c2 = 1.f; }
    else if (t == 1) { cJ = 8.f; c0 = 7.f; c1 = 8.f; c2 = 8.f; }
    else             { cJ = 8.f; c0 = 8.f; c1 = 8.f; c2 = 8.f; }

    const size_t ds = (size_t)Bb * Nn * Dd;
    const size_t base0 = ((((size_t)x * 3 + 0) * Bb + b) * Nn + t) * Dd;

    for (int c = threadIdx.x; c < Dd; c += 256) {
        float G0 = __half2float(g_G[base0 + c]);
        float G1 = __half2float(g_G[base0 + ds + c]);
        float G2 = __half2float(g_G[base0 + 2 * ds + c]);
        float bdc = bd[c];
        float val = cJ * bc[c] + scale * (wc[c]          * (G0 + c0 * bdc) +
                                          wc[Dd + c]     * (G1 + c1 * bdc) +
                                          wc[2 * Dd + c] * (G2 + c2 * bdc));
        val *= 0.125f;
        int h = c >> 6, dd = c & 63;
        g_pool[((((size_t)x * Bb + b) * Hh + h) * Nn + t) * DDd + dd] = val;
    }
}

// ---------------------------------------------------------------------------
// Attention partial v3 (split-KV, two-pass softmax, 2-query register tiling):
// grid (10 tile-pairs, 64 bh), 128 threads. Thread = (qg, ds): queries
// 2qg/2qg+1, dim slice ds*16. Pass 1: dots -> smem + per-query max (no exp).
// Pass 2a: one exp per (q,k) pair, in-place p. Pass 2b: p-weighted V accum.
// ---------------------------------------------------------------------------
__global__ void __launch_bounds__(128) attn_partial() {
    const int qt = c_qt[blockIdx.x];
    const int kc = c_kc[blockIdx.x];
    const int bh = blockIdx.y;
    __shared__ float sK[64][DDd];
    __shared__ float sV[64][DDd];
    __shared__ float sD[64][64];
    __shared__ float sM[64];
    const float* qp = g_pool + ((size_t)0 * Bb * Hh + bh) * Nn * DDd;
    const float* kp = g_pool + ((size_t)1 * Bb * Hh + bh) * Nn * DDd;
    const float* vp = g_pool + ((size_t)2 * Bb * Hh + bh) * Nn * DDd;
    const int tid = threadIdx.x;
    const int qg = tid >> 2;           // 0..31 -> local queries 2qg, 2qg+1
    const int ds4 = (tid & 3) * 16;    // dim slice offset
    const int q0 = qg * 2, q1 = q0 + 1;
    const int qi0 = qt * 64 + q0, qi1 = qi0 + 1;
    const int basek = kc * 64;

    for (int idx = tid; idx < 64 * DDd / 4; idx += 128) {
        ((float4*)&sK[0][0])[idx] = ((const float4*)(kp + (size_t)basek * DDd))[idx];
        ((float4*)&sV[0][0])[idx] = ((const float4*)(vp + (size_t)basek * DDd))[idx];
    }

    float qr0[16], qr1[16];
    #pragma unroll
    for (int d = 0; d < 16; d += 4) {
        *(float4*)&qr0[d] = *(const float4*)(qp + (size_t)qi0 * DDd + ds4 + d);
        *(float4*)&qr1[d] = *(const float4*)(qp + (size_t)qi1 * DDd + ds4 + d);
    }
    __syncthreads();

    // Pass 1: dots + max (no exp)
    const int lim0 = qi0 - basek;      // valid keys: m <= lim
    const int lim1 = qi1 - basek;
    float mi0 = -1e30f, mi1 = -1e30f;
    for (int m = 0; m < 64; m++) {
        float a0 = 0.f, a1 = 0.f;
        #pragma unroll
        for (int d = 0; d < 16; d++) {
            float kk = sK[m][ds4 + d];
            a0 += qr0[d] * kk;
            a1 += qr1[d] * kk;
        }
        a0 += __shfl_xor_sync(0xffffffffu, a0, 1);
        a1 += __shfl_xor_sync(0xffffffffu, a1, 1);
        a0 += __shfl_xor_sync(0xffffffffu, a0, 2);
        a1 += __shfl_xor_sync(0xffffffffu, a1, 2);
        if ((tid & 3) == 0) { sD[m][q0] = a0; sD[m][q1] = a1; }
        if (m <= lim0 && a0 > mi0) mi0 = a0;
        if (m <= lim1 && a1 > mi1) mi1 = a1;
    }
    if ((tid & 3) == 0) { sM[q0] = mi0; sM[q1] = mi1; }
    __syncthreads();

    // Pass 2a: one exp per (q,k) pair, in place (read-then-write same slot)
    for (int idx = tid; idx < 64 * 64; idx += 128) {
        int m = idx >> 6, qq = idx & 63;
        bool valid = (basek + m) <= (qt * 64 + qq);
        sD[m][qq] = valid ? __expf(sD[m][qq] - sM[qq]) : 0.f;
    }
    __syncthreads();

    // Pass 2b: p-weighted V accumulation (pure FMA)
    float acc0[16], acc1[16];
    float li0 = 0.f, li1 = 0.f;
    #pragma unroll
    for (int d = 0; d < 16; d++) { acc0[d] = 0.f; acc1[d] = 0.f; }
    for (int m = 0; m < 64; m++) {
        float p0 = sD[m][q0], p1 = sD[m][q1];
        li0 += p0; li1 += p1;
        #pragma unroll
        for (int d = 0; d < 16; d++) {
            float vv = sV[m][ds4 + d];
            acc0[d] += p0 * vv;
            acc1[d] += p1 * vv;
        }
    }

    const size_t pb0 = ((size_t)bh * Nn + qi0) * 4 + kc;
    const size_t pb1 = ((size_t)bh * Nn + qi1) * 4 + kc;
    if ((tid & 3) == 0) {
        g_pm[pb0] = mi0; g_pl[pb0] = li0;
        g_pm[pb1] = mi1; g_pl[pb1] = li1;
    }
    float* pa0 = g_pacc + pb0 * 64 + ds4;
    float* pa1 = g_pacc + pb1 * 64 + ds4;
    #pragma unroll
    for (int d = 0; d < 16; d += 4) {
        *(float4*)(pa0 + d) = *(float4*)&acc0[d];
        *(float4*)(pa1 + d) = *(float4*)&acc1[d];
    }
}

// ---------------------------------------------------------------------------
// Attention reduce: merge <=4 partials per query, write fp16 merged layout.
// ---------------------------------------------------------------------------
__global__ void __launch_bounds__(128) attn_reduce() {
    const int qt = blockIdx.x;
    const int bh = blockIdx.y;
    const int b = bh >> 4, h = bh & 15;
    const int tid = threadIdx.x;
    const int qi = qt * 64 + (tid >> 1);
    const int hf = (tid & 1) * 32;
    const int np = qt + 1;

    const size_t base = ((size_t)bh * Nn + qi) * 4;
    float M = -1e30f;
    for (int kk = 0; kk < np; kk++) {
        float m = g_pm[base + kk];
        if (m > M) M = m;
    }
    float w[4], L = 0.f;
    for (int kk = 0; kk < np; kk++) {
        w[kk] = __expf(g_pm[base + kk] - M);
        L += g_pl[base + kk] * w[kk];
    }
    float out[32];
    #pragma unroll
    for (int d = 0; d < 32; d++) out[d] = 0.f;
    for (int kk = 0; kk < np; kk++) {
        const float* pa = g_pacc + (base + kk) * 64 + hf;
        float ww = w[kk];
        #pragma unroll
        for (int d = 0; d < 32; d++) out[d] += ww * pa[d];
    }
    float inv = 1.0f / L;
    __half2* outp = (__half2*)(g_OP + ((size_t)(b * Nn + qi)) * Dd + h * 64 + hf);
    #pragma unroll
    for (int d = 0; d < 32; d += 2)
        outp[d >> 1] = __floats2half2_rn(out[d] * inv, out[d + 1] * inv);
}

// ---------------------------------------------------------------------------
extern "C" void kernel_launch(void* const* d_in, const int* in_sizes, int n_in,
                              void* d_out, int out_size) {
    const float* q   = (const float*)d_in[0];
    const float* k   = (const float*)d_in[1];
    const float* v   = (const float*)d_in[2];
    const float* Wq  = (const float*)d_in[3];
    const float* bq  = (const float*)d_in[4];
    const float* Wk  = (const float*)d_in[5];
    const float* bk  = (const float*)d_in[6];
    const float* Wv  = (const float*)d_in[7];
    const float* bv  = (const float*)d_in[8];
    const float* Wup = (const float*)d_in[9];
    const float* bup = (const float*)d_in[10];
    const float* Wc  = (const float*)d_in[11];
    const float* bc  = (const float*)d_in[12];
    const float* wcq = (const float*)d_in[13];
    const float* bcq = (const float*)d_in[14];
    const float* wck = (const float*)d_in[15];
    const float* bck = (const float*)d_in[16];
    const float* wcv = (const float*)d_in[17];
    const float* bcv = (const float*)d_in[18];

    __half *pU, *pWh, *pOP, *pG;
    float *pBias2;
    cudaGetSymbolAddress((void**)&pU, g_U);
    cudaGetSymbolAddress((void**)&pWh, g_Wh);
    cudaGetSymbolAddress((void**)&pOP, g_OP);
    cudaGetSymbolAddress((void**)&pG, g_G);
    cudaGetSymbolAddress((void**)&pBias2, g_bias2);

    const int SM2 = 3 * (128 * 80 + 128 * 80);
    const int SM1 = 3 * (64 * 80 + 128 * 80);
    cudaFuncSetAttribute((const void*)gemm_tc<2, 0>, cudaFuncAttributeMaxDynamicSharedMemorySize, SM2);
    cudaFuncSetAttribute((const void*)gemm_tc<1, 1>, cudaFuncAttributeMaxDynamicSharedMemorySize, SM1);

    // 1. All preprocessing
    prep_kernel<<<dim3(32, 32, 7), 256>>>(q, k, v, Wq, Wk, Wv, Wup, Wc, bup, bc);

    // 2. Fused projection GEMMs
    const size_t wstep = (size_t)1024 * 1024;
    gemm_tc<2, 0><<<dim3(8, 72), 256, SM2>>>(
        pU, pWh + 0 * wstep, pWh + 1 * wstep, pWh + 2 * wstep,
        pG, nullptr, 24);

    // 3. Combine conv weights/biases/scale -> pooled q/k/v
    combine_kernel<<<dim3(Nn, Bb, 3), 256>>>(wcq, bcq, bq, wck, bck, bk, wcv, bcv, bv);

    // 4. Attention partials (two-pass softmax, ncu capture slot)
    attn_partial<<<dim3(10, Bb * Hh), 128>>>();

    // 5. Merge partials -> fp16 merged layout
    attn_reduce<<<dim3(4, Bb * Hh), 128>>>();

    // 6. Final dense with folded Wup+Wc (+bias2), broadcast epilogue to d_out
    gemm_tc<1, 1><<<dim3(8, 16), 256, SM1>>>(
        pOP, pWh + 3 * wstep, pWh + 3 * wstep, pWh + 3 * wstep,
        (void*)d_out, pBias2, 16);
}

// round 15
// speedup vs baseline: 1.3976x; 1.1962x over previous
#include <cuda_runtime.h>
#include <cuda_fp16.h>
#include <stdint.h>
#include <math.h>

#define Bb 4
#define Ss 2048
#define Dd 1024
#define Hh 16
#define Nn 256
#define DDd 64

// ---------------- scratch (device globals; no allocation allowed) ----------
__device__ __half g_U[9216 * 1024];          // pooled GEMM A fp16
__device__ __half g_G[9216 * 1024];          // projection GEMM outputs (fp16)
__device__ __half g_Wh[4 * 1024 * 1024];     // fp16 weights [N,K]: Wq,Wk,Wv,W2
__device__ float g_pool[3 * Bb * Hh * Nn * DDd];  // [x][b][h][t][dd]
__device__ __half g_OP[1024 * 1024];         // attn output, merged [b*t][h*64+dd]
__device__ float g_bias2[1024];              // bc + bup_tiled @ Wc
__device__ float g_pm[64 * 256 * 4];         // split-KV partial max
__device__ float g_pl[64 * 256 * 4];         // split-KV partial sum
__device__ float g_pacc[64 * 256 * 4 * 64];  // split-KV partial acc (unnormalized)

__device__ __constant__ int c_qt[10] = {0,1,1,2,2,2,3,3,3,3};
__device__ __constant__ int c_kc[10] = {0,0,1,0,1,2,0,1,2,3};

// ---------------- PTX helpers ----------------------------------------------
static __device__ __forceinline__ uint32_t smem_u32(const void* p) {
    uint32_t r;
    asm("{ .reg .u64 t; cvta.to.shared.u64 t, %1; cvt.u32.u64 %0, t; }" : "=r"(r) : "l"(p));
    return r;
}
static __device__ __forceinline__ void cp16(uint32_t dst, const void* src) {
    asm volatile("cp.async.cg.shared.global [%0], [%1], 16;" :: "r"(dst), "l"(src));
}
#define CP_COMMIT() asm volatile("cp.async.commit_group;" ::: "memory")
#define CP_WAIT1()  asm volatile("cp.async.wait_group 1;" ::: "memory")

static __device__ __forceinline__ void ldsm_x4(uint32_t* r, uint32_t addr) {
    asm volatile("ldmatrix.sync.aligned.m8n8.x4.shared.b16 {%0,%1,%2,%3}, [%4];"
                 : "=r"(r[0]), "=r"(r[1]), "=r"(r[2]), "=r"(r[3]) : "r"(addr));
}
static __device__ __forceinline__ void mma_f16(float* c, const uint32_t* a, const uint32_t* b) {
    asm volatile(
        "mma.sync.aligned.m16n8k16.row.col.f32.f16.f16.f32 "
        "{%0,%1,%2,%3}, {%4,%5,%6,%7}, {%8,%9}, {%0,%1,%2,%3};"
        : "+f"(c[0]), "+f"(c[1]), "+f"(c[2]), "+f"(c[3])
        : "r"(a[0]), "r"(a[1]), "r"(a[2]), "r"(a[3]), "r"(b[0]), "r"(b[1]));
}

static __device__ __forceinline__ float4 f4add(float4 a, float4 b) {
    return make_float4(a.x + b.x, a.y + b.y, a.z + b.z, a.w + b.w);
}

// ---------------------------------------------------------------------------
// PREP kernel: all independent preprocessing, dispatched on blockIdx.z.
// ---------------------------------------------------------------------------
#define TSTEP 8
__global__ void __launch_bounds__(256) prep_kernel(
        const float* __restrict__ q, const float* __restrict__ k, const float* __restrict__ v,
        const float* __restrict__ Wq, const float* __restrict__ Wk, const float* __restrict__ Wv,
        const float* __restrict__ Wup, const float* __restrict__ Wc,
        const float* __restrict__ bup, const float* __restrict__ bc) {
    const int z = blockIdx.z;
    const int tid = threadIdx.x;

    if (z < 3) {
        const int b = blockIdx.y;
        if (b >= Bb) return;
        const int tr = blockIdx.x;
        const float* src = (z == 0) ? q : ((z == 1) ? k : v);
        const float4* S = (const float4*)(src + (size_t)b * Ss * Dd);
        const int c4 = tid;
        const int t0 = tr * TSTEP;

        float4 zero = make_float4(0.f, 0.f, 0.f, 0.f);
        int r0 = 8 * t0 - 9, r1 = 8 * t0 - 8;
        float4 prev0 = (r0 >= 0) ? S[(size_t)r0 * 256 + c4] : zero;
        float4 prev1 = (r1 >= 0) ? S[(size_t)r1 * 256 + c4] : zero;

        #pragma unroll
        for (int t = t0; t < t0 + TSTEP; t++) {
            float4 nw[8];
            #pragma unroll
            for (int kk = 0; kk < 8; kk++) {
                int rr = 8 * t - 7 + kk;
                nw[kk] = (rr >= 0) ? S[(size_t)rr * 256 + c4] : zero;
            }
            float4 p6 = f4add(f4add(f4add(nw[0], nw[1]), f4add(nw[2], nw[3])), f4add(nw[4], nw[5]));
            float4 s0 = f4add(f4add(prev0, prev1), p6);
            float4 s1 = f4add(prev1, f4add(p6, nw[6]));
            float4 s2 = f4add(p6, f4add(nw[6], nw[7]));
            float4 sv[3] = {s0, s1, s2};
            #pragma unroll
            for (int d = 0; d < 3; d++) {
                size_t row = (((size_t)(z * 3 + d)) * Bb + b) * Nn + t;
                __half2* dst = (__half2*)g_U + row * 512 + c4 * 2;
                dst[0] = __floats2half2_rn(sv[d].x, sv[d].y);
                dst[1] = __floats2half2_rn(sv[d].z, sv[d].w);
            }
            prev0 = nw[6];
            prev1 = nw[7];
        }
    } else if (z < 6) {
        const float* W = (z == 3) ? Wq : ((z == 4) ? Wk : Wv);
        __half* Oh = g_Wh + (size_t)(z - 3) * 1024 * 1024;
        __shared__ float tile[32][33];
        const int n0 = blockIdx.x * 32, k0 = blockIdx.y * 32;
        const int tx = tid & 31, ty = tid >> 5;
        #pragma unroll
        for (int j = 0; j < 4; j++)
            tile[ty + j * 8][tx] = W[(size_t)(k0 + ty + j * 8) * 1024 + n0 + tx];
        __syncthreads();
        #pragma unroll
        for (int j = 0; j < 4; j++) {
            float val = tile[tx][ty + j * 8];
            Oh[(size_t)(n0 + ty + j * 8) * 1024 + k0 + tx] = __float2half_rn(val);
        }
    } else {
        const int bx = blockIdx.x;
        const int by = blockIdx.y;
        const int h = by >> 1, ddb = (by & 1) * 32;
        __shared__ float sWup[32][65];
        __shared__ float sWc[64][32];
        for (int idx = tid; idx < 32 * 64; idx += 256) {
            int dd = idx >> 6, j = idx & 63;
            sWup[dd][j] = Wup[(size_t)(ddb + dd) * 64 + j];
        }
        for (int idx = tid; idx < 64 * 32; idx += 256) {
            int j = idx >> 5, cl = idx & 31;
            sWc[j][cl] = Wc[(size_t)(h * 64 + j) * 1024 + bx * 32 + cl];
        }
        __syncthreads();
        const int rl = tid & 31;
        const int c0 = (tid >> 5) * 4;
        float o[4] = {0.f, 0.f, 0.f, 0.f};
        #pragma unroll
        for (int j = 0; j < 64; j++) {
            float a = sWup[rl][j];
            o[0] += a * sWc[j][c0 + 0];
            o[1] += a * sWc[j][c0 + 1];
            o[2] += a * sWc[j][c0 + 2];
            o[3] += a * sWc[j][c0 + 3];
        }
        __half* W2t = g_Wh + (size_t)3 * 1024 * 1024;
        const int r = by * 32 + rl;
        #pragma unroll
        for (int i = 0; i < 4; i++)
            W2t[(size_t)(bx * 32 + c0 + i) * 1024 + r] = __float2half_rn(o[i]);
        if (by == 0) {
            __shared__ float red[32][9];
            int col = tid >> 3, part = tid & 7;
            int c = bx * 32 + col;
            float s = 0.f;
            for (int rr = part * 128; rr < part * 128 + 128; rr++)
                s += bup[rr & 63] * Wc[(size_t)rr * 1024 + c];
            red[col][part] = s;
            __syncthreads();
            if (part == 0) {
                float tot = bc[c];
                #pragma unroll
                for (int i = 0; i < 8; i++) tot += red[col][i];
                g_bias2[c] = tot;
            }
        }
    }
}

// ---------------------------------------------------------------------------
// HMMA fp16 GEMM (3-stage, measured-best): C = A @ B^T, fp32 accum.
// ---------------------------------------------------------------------------
#define BROWS 128

template <int MI, int BCAST>
__global__ void __launch_bounds__(256) gemm_tc(
        const __half* __restrict__ A,
        const __half* __restrict__ B0, const __half* __restrict__ B1,
        const __half* __restrict__ B2,
        void* __restrict__ Cv, const float* __restrict__ bias, int mblocks_per_x) {
    constexpr int CTAM = 64 * MI;
    constexpr int ASZ = CTAM * 80;
    constexpr int BSZ = BROWS * 80;
    constexpr int STAGE = ASZ + BSZ;

    extern __shared__ char dsm[];
    const uint32_t sbase = smem_u32(dsm);
    const int tid = threadIdx.x;
    const int wid = tid >> 5, lane = tid & 31;
    const int bn = blockIdx.x, bm = blockIdx.y;
    const int x = bm / mblocks_per_x;
    const __half* Bh = (x == 0) ? B0 : ((x == 1) ? B1 : B2);

    const int warpM = wid >> 1;
    const int warpN = wid & 1;
    const uint32_t aOff = (uint32_t)((warpM * 16 * MI + (lane & 15)) * 80 + (lane >> 4) * 16);
    const uint32_t bOff = (uint32_t)(ASZ +
        (warpN * 64 + ((lane >> 4) & 1) * 8 + (lane & 7)) * 80 + ((lane >> 3) & 1) * 16);

    float acc[MI][8][4];
    #pragma unroll
    for (int mi = 0; mi < MI; mi++)
        #pragma unroll
        for (int ni = 0; ni < 8; ni++)
            #pragma unroll
            for (int j = 0; j < 4; j++) acc[mi][ni][j] = 0.f;

    auto load_chunk = [&](int ch, int st) {
        const uint32_t bb = sbase + st * STAGE;
        const int kof = ch * 32;
        #pragma unroll
        for (int it = 0; it < MI; it++) {
            int idx = tid + it * 256;
            int r = idx >> 2, qq = idx & 3;
            uint32_t dst = bb + r * 80 + qq * 16;
            size_t g = (size_t)(bm * CTAM + r) * 1024 + kof + qq * 8;
            cp16(dst, A + g);
        }
        #pragma unroll
        for (int it = 0; it < 2; it++) {
            int idx = tid + it * 256;
            int r = idx >> 2, qq = idx & 3;
            uint32_t dst = bb + ASZ + r * 80 + qq * 16;
            size_t g = (size_t)(bn * BROWS + r) * 1024 + kof + qq * 8;
            cp16(dst, Bh + g);
        }
        CP_COMMIT();
    };

    load_chunk(0, 0);
    load_chunk(1, 1);

    for (int i = 0; i < 32; i++) {
        CP_WAIT1();
        __syncthreads();
        const uint32_t bb = sbase + (i % 3) * STAGE;
        #pragma unroll
        for (int kk = 0; kk < 2; kk++) {
            uint32_t ah[MI][4];
            #pragma unroll
            for (int mi = 0; mi < MI; mi++)
                ldsm_x4(ah[mi], bb + aOff + mi * 16 * 80 + kk * 32);
            #pragma unroll
            for (int p = 0; p < 4; p++) {
                uint32_t b4[4];
                ldsm_x4(b4, bb + bOff + p * 16 * 80 + kk * 32);
                #pragma unroll
                for (int mi = 0; mi < MI; mi++) {
                    mma_f16(acc[mi][2 * p],     ah[mi], b4);
                    mma_f16(acc[mi][2 * p + 1], ah[mi], b4 + 2);
                }
            }
        }
        if (i + 2 < 32) load_chunk(i + 2, (i + 2) % 3);
        else CP_COMMIT();
    }

    const int row0 = bm * CTAM + warpM * 16 * MI + (lane >> 2);
    const int col0 = bn * 128 + warpN * 64 + (lane & 3) * 2;
    #pragma unroll
    for (int mi = 0; mi < MI; mi++) {
        #pragma unroll
        for (int ni = 0; ni < 8; ni++) {
            int r = row0 + mi * 16;
            int c = col0 + ni * 8;
            if (BCAST) {
                float* C = (float*)Cv;
                float b0 = bias ? bias[c] : 0.f, b1 = bias ? bias[c + 1] : 0.f;
                float2 v0 = make_float2(acc[mi][ni][0] + b0, acc[mi][ni][1] + b1);
                float2 v1 = make_float2(acc[mi][ni][2] + b0, acc[mi][ni][3] + b1);
                int rb = r >> 8, rt = r & 255;
                float* o0 = C + ((size_t)rb * Ss + rt * 8) * 1024 + c;
                int r8 = r + 8;
                int rb2 = r8 >> 8, rt2 = r8 & 255;
                float* o1 = C + ((size_t)rb2 * Ss + rt2 * 8) * 1024 + c;
                #pragma unroll
                for (int rep = 0; rep < 8; rep++) {
                    *(float2*)(o0 + rep * 1024) = v0;
                    *(float2*)(o1 + rep * 1024) = v1;
                }
            } else {
                __half* C = (__half*)Cv;
                *(__half2*)&C[(size_t)r * 1024 + c] =
                    __floats2half2_rn(acc[mi][ni][0], acc[mi][ni][1]);
                *(__half2*)&C[(size_t)(r + 8) * 1024 + c] =
                    __floats2half2_rn(acc[mi][ni][2], acc[mi][ni][3]);
            }
        }
    }
}

// ---------------------------------------------------------------------------
// Combine: fold conv weights + biases + norm scale + /8 into pooled q/k/v.
// ---------------------------------------------------------------------------
__global__ void __launch_bounds__(256) combine_kernel(
        const float* __restrict__ wcq, const float* __restrict__ bcq, const float* __restrict__ bq,
        const float* __restrict__ wck, const float* __restrict__ bck, const float* __restrict__ bk,
        const float* __restrict__ wcv, const float* __restrict__ bcv, const float* __restrict__ bv) {
    const int t = blockIdx.x, b = blockIdx.y, x = blockIdx.z;
    const float* wc = (x == 0) ? wcq : ((x == 1) ? wck : wcv);
    const float* bc = (x == 0) ? bcq : ((x == 1) ? bck : bcv);
    const float* bd = (x == 0) ? bq  : ((x == 1) ? bk  : bv);
    const float scale = (x == 2) ? 1.0f : 0.35355339059327379f;

    float cJ, c0, c1, c2;
    if (t == 0)      { cJ = 1.f; c0 = 0.f; c1 = 0.f; c2 = 1.f; }
    else if (t == 1) { cJ = 8.f; c0 = 7.f; c1 = 8.f; c2 = 8.f; }
    else             { cJ = 8.f; c0 = 8.f; c1 = 8.f; c2 = 8.f; }

    const size_t ds = (size_t)Bb * Nn * Dd;
    const size_t base0 = ((((size_t)x * 3 + 0) * Bb + b) * Nn + t) * Dd;

    for (int c = threadIdx.x; c < Dd; c += 256) {
        float G0 = __half2float(g_G[base0 + c]);
        float G1 = __half2float(g_G[base0 + ds + c]);
        float G2 = __half2float(g_G[base0 + 2 * ds + c]);
        float bdc = bd[c];
        float val = cJ * bc[c] + scale * (wc[c]          * (G0 + c0 * bdc) +
                                          wc[Dd + c]     * (G1 + c1 * bdc) +
                                          wc[2 * Dd + c] * (G2 + c2 * bdc));
        val *= 0.125f;
        int h = c >> 6, dd = c & 63;
        g_pool[((((size_t)x * Bb + b) * Hh + h) * Nn + t) * DDd + dd] = val;
    }
}

// ---------------------------------------------------------------------------
// Attention partial v4 (tensor-core): grid (10 pairs, 64 bh), 128 thr (4 warps).
// Per CTA: load Q/K/V 64x64 fp32 tiles, split fp16 hi/lo in smem (V transposed
// for the B operand). S = Q@K^T via 3-term mma (fp32 accurate). Masked exp with
// exact per-query max -> P split hi/lo. O = P@V via 3-term mma. Writes split-KV
// partials (m, l, unnormalized acc) as before.
// SMEM rows padded to 144B (proven conflict-free pattern at stride 80; 144 is
// also 16B-aligned for ldmatrix).
// ---------------------------------------------------------------------------
#define TS 144                      // tile row stride in bytes (64 halfs + pad)
#define OFF_QH 0
#define OFF_QL (64 * TS)
#define OFF_KH (2 * 64 * TS)
#define OFF_KL (3 * 64 * TS)
#define OFF_VH (4 * 64 * TS)
#define OFF_VL (5 * 64 * TS)
#define OFF_S  (6 * 64 * TS)        // 64 x 68 floats
#define ATTN_SMEM (OFF_S + 64 * 68 * 4)
#define OFF_PH OFF_QH               // P reuses Q tiles
#define OFF_PL OFF_QL

__global__ void __launch_bounds__(128) attn_partial() {
    extern __shared__ char dsm[];
    const uint32_t sb = smem_u32(dsm);
    float* sS = (float*)(dsm + OFF_S);
    const int qt = c_qt[blockIdx.x];
    const int kc = c_kc[blockIdx.x];
    const int bh = blockIdx.y;
    const int tid = threadIdx.x;
    const int wid = tid >> 5, lane = tid & 31;
    const float* qp = g_pool + ((size_t)0 * Bb * Hh + bh) * Nn * DDd + (size_t)qt * 64 * DDd;
    const float* kp = g_pool + ((size_t)1 * Bb * Hh + bh) * Nn * DDd + (size_t)kc * 64 * DDd;
    const float* vp = g_pool + ((size_t)2 * Bb * Hh + bh) * Nn * DDd + (size_t)kc * 64 * DDd;

    // ---- load + split Q, K (natural layout) and V (transposed) ----
    for (int it = 0; it < 8; it++) {
        int idx = tid + it * 128;          // 1024 float4 slots: row = idx>>4, f4 = idx&15
        int row = idx >> 4, f4 = idx & 15;
        float4 qv = *(const float4*)(qp + (size_t)row * 64 + f4 * 4);
        float4 kv = *(const float4*)(kp + (size_t)row * 64 + f4 * 4);
        float4 vv = *(const float4*)(vp + (size_t)row * 64 + f4 * 4);
        float qa[4] = {qv.x, qv.y, qv.z, qv.w};
        float ka[4] = {kv.x, kv.y, kv.z, kv.w};
        float va[4] = {vv.x, vv.y, vv.z, vv.w};
        __half qh[4], ql[4], kh[4], kl[4];
        #pragma unroll
        for (int j = 0; j < 4; j++) {
            qh[j] = __float2half_rn(qa[j]); ql[j] = __float2half_rn(qa[j] - __half2float(qh[j]));
            kh[j] = __float2half_rn(ka[j]); kl[j] = __float2half_rn(ka[j] - __half2float(kh[j]));
        }
        char* bq_ = dsm + OFF_QH + row * TS + f4 * 8;
        char* bql = dsm + OFF_QL + row * TS + f4 * 8;
        char* bk_ = dsm + OFF_KH + row * TS + f4 * 8;
        char* bkl = dsm + OFF_KL + row * TS + f4 * 8;
        ((__half2*)bq_)[0] = __halves2half2(qh[0], qh[1]);
        ((__half2*)bq_)[1] = __halves2half2(qh[2], qh[3]);
        ((__half2*)bql)[0] = __halves2half2(ql[0], ql[1]);
        ((__half2*)bql)[1] = __halves2half2(ql[2], ql[3]);
        ((__half2*)bk_)[0] = __halves2half2(kh[0], kh[1]);
        ((__half2*)bk_)[1] = __halves2half2(kh[2], kh[3]);
        ((__half2*)bkl)[0] = __halves2half2(kl[0], kl[1]);
        ((__half2*)bkl)[1] = __halves2half2(kl[2], kl[3]);
        // V transposed: element (row=m, dd=f4*4+j) -> sVt[dd][m]
        #pragma unroll
        for (int j = 0; j < 4; j++) {
            int dd = f4 * 4 + j;
            __half vh = __float2half_rn(va[j]);
            __half vl = __float2half_rn(va[j] - __half2float(vh));
            *(__half*)(dsm + OFF_VH + dd * TS + row * 2) = vh;
            *(__half*)(dsm + OFF_VL + dd * TS + row * 2) = vl;
        }
    }
    __syncthreads();

    // ---- S = Q @ K^T (3-term split mma). Warp w -> S rows [w*16, w*16+16).
    const uint32_t aOff = (uint32_t)((wid * 16 + (lane & 15)) * TS + (lane >> 4) * 16);
    const uint32_t bOff = (uint32_t)((((lane >> 4) & 1) * 8 + (lane & 7)) * TS + ((lane >> 3) & 1) * 16);
    {
        float acc[8][4];
        #pragma unroll
        for (int ni = 0; ni < 8; ni++)
            #pragma unroll
            for (int j = 0; j < 4; j++) acc[ni][j] = 0.f;

        const uint32_t aBase[3] = {sb + OFF_QH, sb + OFF_QH, sb + OFF_QL};
        const uint32_t bBase[3] = {sb + OFF_KH, sb + OFF_KL, sb + OFF_KH};
        #pragma unroll
        for (int t = 0; t < 3; t++) {
            #pragma unroll
            for (int kk = 0; kk < 4; kk++) {
                uint32_t ah[4];
                ldsm_x4(ah, aBase[t] + aOff + kk * 32);
                #pragma unroll
                for (int p = 0; p < 4; p++) {
                    uint32_t b4[4];
                    ldsm_x4(b4, bBase[t] + bOff + p * 16 * TS + kk * 32);
                    mma_f16(acc[2 * p],     ah, b4);
                    mma_f16(acc[2 * p + 1], ah, b4 + 2);
                }
            }
        }
        const int r0 = wid * 16 + (lane >> 2);
        const int cb = (lane & 3) * 2;
        #pragma unroll
        for (int ni = 0; ni < 8; ni++) {
            int c = ni * 8 + cb;
            *(float2*)&sS[r0 * 68 + c] = make_float2(acc[ni][0], acc[ni][1]);
            *(float2*)&sS[(r0 + 8) * 68 + c] = make_float2(acc[ni][2], acc[ni][3]);
        }
    }
    __syncthreads();

    // ---- softmax partials: 2 threads/query (tid>>1 = q, tid&1 = m-half) ----
    {
        const int qq = tid >> 1;
        const int mh = (tid & 1) * 32;
        const int qi = qt * 64 + qq;
        const int lim = qi - kc * 64;          // valid keys m <= lim
        float mx = -1e30f;
        for (int m = mh; m < mh + 32; m++) {
            if (m <= lim) {
                float s = sS[qq * 68 + m];
                if (s > mx) mx = s;
            }
        }
        float om = __shfl_xor_sync(0xffffffffu, mx, 1);
        if (om > mx) mx = om;
        float li = 0.f;
        for (int m = mh; m < mh + 32; m++) {
            float p = 0.f;
            if (m <= lim) p = __expf(sS[qq * 68 + m] - mx);
            li += p;
            __half ph = __float2half_rn(p);
            *(__half*)(dsm + OFF_PH + qq * TS + m * 2) = ph;
            *(__half*)(dsm + OFF_PL + qq * TS + m * 2) = __float2half_rn(p - __half2float(ph));
        }
        li += __shfl_xor_sync(0xffffffffu, li, 1);
        if ((tid & 1) == 0) {
            const size_t pb = ((size_t)bh * Nn + qi) * 4 + kc;
            g_pm[pb] = mx;
            g_pl[pb] = li;
        }
    }
    __syncthreads();

    // ---- O = P @ Vt (3-term split mma). Same fragment patterns. ----
    {
        float acc[8][4];
        #pragma unroll
        for (int ni = 0; ni < 8; ni++)
            #pragma unroll
            for (int j = 0; j < 4; j++) acc[ni][j] = 0.f;

        const uint32_t aBase[3] = {sb + OFF_PH, sb + OFF_PH, sb + OFF_PL};
        const uint32_t bBase[3] = {sb + OFF_VH, sb + OFF_VL, sb + OFF_VH};
        #pragma unroll
        for (int t = 0; t < 3; t++) {
            #pragma unroll
            for (int kk = 0; kk < 4; kk++) {
                uint32_t ah[4];
                ldsm_x4(ah, aBase[t] + aOff + kk * 32);
                #pragma unroll
                for (int p = 0; p < 4; p++) {
                    uint32_t b4[4];
                    ldsm_x4(b4, bBase[t] + bOff + p * 16 * TS + kk * 32);
                    mma_f16(acc[2 * p],     ah, b4);
                    mma_f16(acc[2 * p + 1], ah, b4 + 2);
                }
            }
        }
        const int r0 = wid * 16 + (lane >> 2);
        const int cb = (lane & 3) * 2;
        const size_t pb0 = ((size_t)bh * Nn + qt * 64 + r0) * 4 + kc;
        const size_t pb1 = ((size_t)bh * Nn + qt * 64 + r0 + 8) * 4 + kc;
        #pragma unroll
        for (int ni = 0; ni < 8; ni++) {
            int dd = ni * 8 + cb;
            *(float2*)&g_pacc[pb0 * 64 + dd] = make_float2(acc[ni][0], acc[ni][1]);
            *(float2*)&g_pacc[pb1 * 64 + dd] = make_float2(acc[ni][2], acc[ni][3]);
        }
    }
}

// ---------------------------------------------------------------------------
// Attention reduce: merge <=4 partials per query, write fp16 merged layout.
// ---------------------------------------------------------------------------
__global__ void __launch_bounds__(128) attn_reduce() {
    const int qt = blockIdx.x;
    const int bh = blockIdx.y;
    const int b = bh >> 4, h = bh & 15;
    const int tid = threadIdx.x;
    const int qi = qt * 64 + (tid >> 1);
    const int hf = (tid & 1) * 32;
    const int np = qt + 1;

    const size_t base = ((size_t)bh * Nn + qi) * 4;
    float M = -1e30f;
    for (int kk = 0; kk < np; kk++) {
        float m = g_pm[base + kk];
        if (m > M) M = m;
    }
    float w[4], L = 0.f;
    for (int kk = 0; kk < np; kk++) {
        w[kk] = __expf(g_pm[base + kk] - M);
        L += g_pl[base + kk] * w[kk];
    }
    float out[32];
    #pragma unroll
    for (int d = 0; d < 32; d++) out[d] = 0.f;
    for (int kk = 0; kk < np; kk++) {
        const float* pa = g_pacc + (base + kk) * 64 + hf;
        float ww = w[kk];
        #pragma unroll
        for (int d = 0; d < 32; d++) out[d] += ww * pa[d];
    }
    float inv = 1.0f / L;
    __half2* outp = (__half2*)(g_OP + ((size_t)(b * Nn + qi)) * Dd + h * 64 + hf);
    #pragma unroll
    for (int d = 0; d < 32; d += 2)
        outp[d >> 1] = __floats2half2_rn(out[d] * inv, out[d + 1] * inv);
}

// ---------------------------------------------------------------------------
extern "C" void kernel_launch(void* const* d_in, const int* in_sizes, int n_in,
                              void* d_out, int out_size) {
    const float* q   = (const float*)d_in[0];
    const float* k   = (const float*)d_in[1];
    const float* v   = (const float*)d_in[2];
    const float* Wq  = (const float*)d_in[3];
    const float* bq  = (const float*)d_in[4];
    const float* Wk  = (const float*)d_in[5];
    const float* bk  = (const float*)d_in[6];
    const float* Wv  = (const float*)d_in[7];
    const float* bv  = (const float*)d_in[8];
    const float* Wup = (const float*)d_in[9];
    const float* bup = (const float*)d_in[10];
    const float* Wc  = (const float*)d_in[11];
    const float* bc  = (const float*)d_in[12];
    const float* wcq = (const float*)d_in[13];
    const float* bcq = (const float*)d_in[14];
    const float* wck = (const float*)d_in[15];
    const float* bck = (const float*)d_in[16];
    const float* wcv = (const float*)d_in[17];
    const float* bcv = (const float*)d_in[18];

    __half *pU, *pWh, *pOP, *pG;
    float *pBias2;
    cudaGetSymbolAddress((void**)&pU, g_U);
    cudaGetSymbolAddress((void**)&pWh, g_Wh);
    cudaGetSymbolAddress((void**)&pOP, g_OP);
    cudaGetSymbolAddress((void**)&pG, g_G);
    cudaGetSymbolAddress((void**)&pBias2, g_bias2);

    const int SM2 = 3 * (128 * 80 + 128 * 80);
    const int SM1 = 3 * (64 * 80 + 128 * 80);
    cudaFuncSetAttribute((const void*)gemm_tc<2, 0>, cudaFuncAttributeMaxDynamicSharedMemorySize, SM2);
    cudaFuncSetAttribute((const void*)gemm_tc<1, 1>, cudaFuncAttributeMaxDynamicSharedMemorySize, SM1);
    cudaFuncSetAttribute((const void*)attn_partial, cudaFuncAttributeMaxDynamicSharedMemorySize, ATTN_SMEM);

    // 1. All preprocessing
    prep_kernel<<<dim3(32, 32, 7), 256>>>(q, k, v, Wq, Wk, Wv, Wup, Wc, bup, bc);

    // 2. Fused projection GEMMs
    const size_t wstep = (size_t)1024 * 1024;
    gemm_tc<2, 0><<<dim3(8, 72), 256, SM2>>>(
        pU, pWh + 0 * wstep, pWh + 1 * wstep, pWh + 2 * wstep,
        pG, nullptr, 24);

    // 3. Combine conv weights/biases/scale -> pooled q/k/v
    combine_kernel<<<dim3(Nn, Bb, 3), 256>>>(wcq, bcq, bq, wck, bck, bk, wcv, bcv, bv);

    // 4. Attention partials (tensor-core, ncu capture slot)
    attn_partial<<<dim3(10, Bb * Hh), 128, ATTN_SMEM>>>();

    // 5. Merge partials -> fp16 merged layout
    attn_reduce<<<dim3(4, Bb * Hh), 128>>>();

    // 6. Final dense with folded Wup+Wc (+bias2), broadcast epilogue to d_out
    gemm_tc<1, 1><<<dim3(8, 16), 256, SM1>>>(
        pOP, pWh + 3 * wstep, pWh + 3 * wstep, pWh + 3 * wstep,
        (void*)d_out, pBias2, 16);
}

// round 16
// speedup vs baseline: 1.4137x; 1.0115x over previous
#include <cuda_runtime.h>
#include <cuda_fp16.h>
#include <stdint.h>
#include <math.h>

#define Bb 4
#define Ss 2048
#define Dd 1024
#define Hh 16
#define Nn 256
#define DDd 64

// ---------------- scratch (device globals; no allocation allowed) ----------
__device__ __half g_U[9216 * 1024];          // pooled GEMM A fp16
__device__ __half g_G[9216 * 1024];          // projection GEMM outputs (fp16)
__device__ __half g_Wh[4 * 1024 * 1024];     // fp16 weights [N,K]: Wq,Wk,Wv,W2
__device__ float g_pool[3 * Bb * Hh * Nn * DDd];  // [x][b][h][t][dd]
__device__ __half g_OP[1024 * 1024];         // attn output, merged [b*t][h*64+dd]
__device__ float g_bias2[1024];              // bc + bup_tiled @ Wc
__device__ float g_pm[64 * 256 * 4];         // split-KV partial max
__device__ float g_pl[64 * 256 * 4];         // split-KV partial sum
__device__ float g_pacc[64 * 256 * 4 * 64];  // split-KV partial acc (unnormalized)

__device__ __constant__ int c_qt[10] = {0,1,1,2,2,2,3,3,3,3};
__device__ __constant__ int c_kc[10] = {0,0,1,0,1,2,0,1,2,3};

// ---------------- PTX helpers ----------------------------------------------
static __device__ __forceinline__ uint32_t smem_u32(const void* p) {
    uint32_t r;
    asm("{ .reg .u64 t; cvta.to.shared.u64 t, %1; cvt.u32.u64 %0, t; }" : "=r"(r) : "l"(p));
    return r;
}
static __device__ __forceinline__ void cp16(uint32_t dst, const void* src) {
    asm volatile("cp.async.cg.shared.global [%0], [%1], 16;" :: "r"(dst), "l"(src));
}
#define CP_COMMIT() asm volatile("cp.async.commit_group;" ::: "memory")
#define CP_WAIT1()  asm volatile("cp.async.wait_group 1;" ::: "memory")

static __device__ __forceinline__ void ldsm_x4(uint32_t* r, uint32_t addr) {
    asm volatile("ldmatrix.sync.aligned.m8n8.x4.shared.b16 {%0,%1,%2,%3}, [%4];"
                 : "=r"(r[0]), "=r"(r[1]), "=r"(r[2]), "=r"(r[3]) : "r"(addr));
}
static __device__ __forceinline__ void mma_f16(float* c, const uint32_t* a, const uint32_t* b) {
    asm volatile(
        "mma.sync.aligned.m16n8k16.row.col.f32.f16.f16.f32 "
        "{%0,%1,%2,%3}, {%4,%5,%6,%7}, {%8,%9}, {%0,%1,%2,%3};"
        : "+f"(c[0]), "+f"(c[1]), "+f"(c[2]), "+f"(c[3])
        : "r"(a[0]), "r"(a[1]), "r"(a[2]), "r"(a[3]), "r"(b[0]), "r"(b[1]));
}

static __device__ __forceinline__ float4 f4add(float4 a, float4 b) {
    return make_float4(a.x + b.x, a.y + b.y, a.z + b.z, a.w + b.w);
}

// ---------------------------------------------------------------------------
// PREP kernel: all independent preprocessing, dispatched on blockIdx.z.
// ---------------------------------------------------------------------------
#define TSTEP 8
__global__ void __launch_bounds__(256) prep_kernel(
        const float* __restrict__ q, const float* __restrict__ k, const float* __restrict__ v,
        const float* __restrict__ Wq, const float* __restrict__ Wk, const float* __restrict__ Wv,
        const float* __restrict__ Wup, const float* __restrict__ Wc,
        const float* __restrict__ bup, const float* __restrict__ bc) {
    const int z = blockIdx.z;
    const int tid = threadIdx.x;

    if (z < 3) {
        const int b = blockIdx.y;
        if (b >= Bb) return;
        const int tr = blockIdx.x;
        const float* src = (z == 0) ? q : ((z == 1) ? k : v);
        const float4* S = (const float4*)(src + (size_t)b * Ss * Dd);
        const int c4 = tid;
        const int t0 = tr * TSTEP;

        float4 zero = make_float4(0.f, 0.f, 0.f, 0.f);
        int r0 = 8 * t0 - 9, r1 = 8 * t0 - 8;
        float4 prev0 = (r0 >= 0) ? S[(size_t)r0 * 256 + c4] : zero;
        float4 prev1 = (r1 >= 0) ? S[(size_t)r1 * 256 + c4] : zero;

        #pragma unroll
        for (int t = t0; t < t0 + TSTEP; t++) {
            float4 nw[8];
            #pragma unroll
            for (int kk = 0; kk < 8; kk++) {
                int rr = 8 * t - 7 + kk;
                nw[kk] = (rr >= 0) ? S[(size_t)rr * 256 + c4] : zero;
            }
            float4 p6 = f4add(f4add(f4add(nw[0], nw[1]), f4add(nw[2], nw[3])), f4add(nw[4], nw[5]));
            float4 s0 = f4add(f4add(prev0, prev1), p6);
            float4 s1 = f4add(prev1, f4add(p6, nw[6]));
            float4 s2 = f4add(p6, f4add(nw[6], nw[7]));
            float4 sv[3] = {s0, s1, s2};
            #pragma unroll
            for (int d = 0; d < 3; d++) {
                size_t row = (((size_t)(z * 3 + d)) * Bb + b) * Nn + t;
                __half2* dst = (__half2*)g_U + row * 512 + c4 * 2;
                dst[0] = __floats2half2_rn(sv[d].x, sv[d].y);
                dst[1] = __floats2half2_rn(sv[d].z, sv[d].w);
            }
            prev0 = nw[6];
            prev1 = nw[7];
        }
    } else if (z < 6) {
        const float* W = (z == 3) ? Wq : ((z == 4) ? Wk : Wv);
        __half* Oh = g_Wh + (size_t)(z - 3) * 1024 * 1024;
        __shared__ float tile[32][33];
        const int n0 = blockIdx.x * 32, k0 = blockIdx.y * 32;
        const int tx = tid & 31, ty = tid >> 5;
        #pragma unroll
        for (int j = 0; j < 4; j++)
            tile[ty + j * 8][tx] = W[(size_t)(k0 + ty + j * 8) * 1024 + n0 + tx];
        __syncthreads();
        #pragma unroll
        for (int j = 0; j < 4; j++) {
            float val = tile[tx][ty + j * 8];
            Oh[(size_t)(n0 + ty + j * 8) * 1024 + k0 + tx] = __float2half_rn(val);
        }
    } else {
        const int bx = blockIdx.x;
        const int by = blockIdx.y;
        const int h = by >> 1, ddb = (by & 1) * 32;
        __shared__ float sWup[32][65];
        __shared__ float sWc[64][32];
        for (int idx = tid; idx < 32 * 64; idx += 256) {
            int dd = idx >> 6, j = idx & 63;
            sWup[dd][j] = Wup[(size_t)(ddb + dd) * 64 + j];
        }
        for (int idx = tid; idx < 64 * 32; idx += 256) {
            int j = idx >> 5, cl = idx & 31;
            sWc[j][cl] = Wc[(size_t)(h * 64 + j) * 1024 + bx * 32 + cl];
        }
        __syncthreads();
        const int rl = tid & 31;
        const int c0 = (tid >> 5) * 4;
        float o[4] = {0.f, 0.f, 0.f, 0.f};
        #pragma unroll
        for (int j = 0; j < 64; j++) {
            float a = sWup[rl][j];
            o[0] += a * sWc[j][c0 + 0];
            o[1] += a * sWc[j][c0 + 1];
            o[2] += a * sWc[j][c0 + 2];
            o[3] += a * sWc[j][c0 + 3];
        }
        __half* W2t = g_Wh + (size_t)3 * 1024 * 1024;
        const int r = by * 32 + rl;
        #pragma unroll
        for (int i = 0; i < 4; i++)
            W2t[(size_t)(bx * 32 + c0 + i) * 1024 + r] = __float2half_rn(o[i]);
        if (by == 0) {
            __shared__ float red[32][9];
            int col = tid >> 3, part = tid & 7;
            int c = bx * 32 + col;
            float s = 0.f;
            for (int rr = part * 128; rr < part * 128 + 128; rr++)
                s += bup[rr & 63] * Wc[(size_t)rr * 1024 + c];
            red[col][part] = s;
            __syncthreads();
            if (part == 0) {
                float tot = bc[c];
                #pragma unroll
                for (int i = 0; i < 8; i++) tot += red[col][i];
                g_bias2[c] = tot;
            }
        }
    }
}

// ---------------------------------------------------------------------------
// HMMA fp16 GEMM (3-stage, measured-best): C = A @ B^T, fp32 accum.
// ---------------------------------------------------------------------------
#define BROWS 128

template <int MI, int BCAST>
__global__ void __launch_bounds__(256) gemm_tc(
        const __half* __restrict__ A,
        const __half* __restrict__ B0, const __half* __restrict__ B1,
        const __half* __restrict__ B2,
        void* __restrict__ Cv, const float* __restrict__ bias, int mblocks_per_x) {
    constexpr int CTAM = 64 * MI;
    constexpr int ASZ = CTAM * 80;
    constexpr int BSZ = BROWS * 80;
    constexpr int STAGE = ASZ + BSZ;

    extern __shared__ char dsm[];
    const uint32_t sbase = smem_u32(dsm);
    const int tid = threadIdx.x;
    const int wid = tid >> 5, lane = tid & 31;
    const int bn = blockIdx.x, bm = blockIdx.y;
    const int x = bm / mblocks_per_x;
    const __half* Bh = (x == 0) ? B0 : ((x == 1) ? B1 : B2);

    const int warpM = wid >> 1;
    const int warpN = wid & 1;
    const uint32_t aOff = (uint32_t)((warpM * 16 * MI + (lane & 15)) * 80 + (lane >> 4) * 16);
    const uint32_t bOff = (uint32_t)(ASZ +
        (warpN * 64 + ((lane >> 4) & 1) * 8 + (lane & 7)) * 80 + ((lane >> 3) & 1) * 16);

    float acc[MI][8][4];
    #pragma unroll
    for (int mi = 0; mi < MI; mi++)
        #pragma unroll
        for (int ni = 0; ni < 8; ni++)
            #pragma unroll
            for (int j = 0; j < 4; j++) acc[mi][ni][j] = 0.f;

    auto load_chunk = [&](int ch, int st) {
        const uint32_t bb = sbase + st * STAGE;
        const int kof = ch * 32;
        #pragma unroll
        for (int it = 0; it < MI; it++) {
            int idx = tid + it * 256;
            int r = idx >> 2, qq = idx & 3;
            uint32_t dst = bb + r * 80 + qq * 16;
            size_t g = (size_t)(bm * CTAM + r) * 1024 + kof + qq * 8;
            cp16(dst, A + g);
        }
        #pragma unroll
        for (int it = 0; it < 2; it++) {
            int idx = tid + it * 256;
            int r = idx >> 2, qq = idx & 3;
            uint32_t dst = bb + ASZ + r * 80 + qq * 16;
            size_t g = (size_t)(bn * BROWS + r) * 1024 + kof + qq * 8;
            cp16(dst, Bh + g);
        }
        CP_COMMIT();
    };

    load_chunk(0, 0);
    load_chunk(1, 1);

    for (int i = 0; i < 32; i++) {
        CP_WAIT1();
        __syncthreads();
        const uint32_t bb = sbase + (i % 3) * STAGE;
        #pragma unroll
        for (int kk = 0; kk < 2; kk++) {
            uint32_t ah[MI][4];
            #pragma unroll
            for (int mi = 0; mi < MI; mi++)
                ldsm_x4(ah[mi], bb + aOff + mi * 16 * 80 + kk * 32);
            #pragma unroll
            for (int p = 0; p < 4; p++) {
                uint32_t b4[4];
                ldsm_x4(b4, bb + bOff + p * 16 * 80 + kk * 32);
                #pragma unroll
                for (int mi = 0; mi < MI; mi++) {
                    mma_f16(acc[mi][2 * p],     ah[mi], b4);
                    mma_f16(acc[mi][2 * p + 1], ah[mi], b4 + 2);
                }
            }
        }
        if (i + 2 < 32) load_chunk(i + 2, (i + 2) % 3);
        else CP_COMMIT();
    }

    const int row0 = bm * CTAM + warpM * 16 * MI + (lane >> 2);
    const int col0 = bn * 128 + warpN * 64 + (lane & 3) * 2;
    #pragma unroll
    for (int mi = 0; mi < MI; mi++) {
        #pragma unroll
        for (int ni = 0; ni < 8; ni++) {
            int r = row0 + mi * 16;
            int c = col0 + ni * 8;
            if (BCAST) {
                float* C = (float*)Cv;
                float b0 = bias ? bias[c] : 0.f, b1 = bias ? bias[c + 1] : 0.f;
                float2 v0 = make_float2(acc[mi][ni][0] + b0, acc[mi][ni][1] + b1);
                float2 v1 = make_float2(acc[mi][ni][2] + b0, acc[mi][ni][3] + b1);
                int rb = r >> 8, rt = r & 255;
                float* o0 = C + ((size_t)rb * Ss + rt * 8) * 1024 + c;
                int r8 = r + 8;
                int rb2 = r8 >> 8, rt2 = r8 & 255;
                float* o1 = C + ((size_t)rb2 * Ss + rt2 * 8) * 1024 + c;
                #pragma unroll
                for (int rep = 0; rep < 8; rep++) {
                    *(float2*)(o0 + rep * 1024) = v0;
                    *(float2*)(o1 + rep * 1024) = v1;
                }
            } else {
                __half* C = (__half*)Cv;
                *(__half2*)&C[(size_t)r * 1024 + c] =
                    __floats2half2_rn(acc[mi][ni][0], acc[mi][ni][1]);
                *(__half2*)&C[(size_t)(r + 8) * 1024 + c] =
                    __floats2half2_rn(acc[mi][ni][2], acc[mi][ni][3]);
            }
        }
    }
}

// ---------------------------------------------------------------------------
// Combine (vectorized, 4 channels/thread): fold conv weights + biases +
// norm scale + /8 into pooled q/k/v.
// ---------------------------------------------------------------------------
__global__ void __launch_bounds__(256) combine_kernel(
        const float* __restrict__ wcq, const float* __restrict__ bcq, const float* __restrict__ bq,
        const float* __restrict__ wck, const float* __restrict__ bck, const float* __restrict__ bk,
        const float* __restrict__ wcv, const float* __restrict__ bcv, const float* __restrict__ bv) {
    const int t = blockIdx.x, b = blockIdx.y, x = blockIdx.z;
    const float* wc = (x == 0) ? wcq : ((x == 1) ? wck : wcv);
    const float* bc = (x == 0) ? bcq : ((x == 1) ? bck : bcv);
    const float* bd = (x == 0) ? bq  : ((x == 1) ? bk  : bv);
    const float scale = (x == 2) ? 1.0f : 0.35355339059327379f;

    float cJ, c0, c1, c2;
    if (t == 0)      { cJ = 1.f; c0 = 0.f; c1 = 0.f; c2 = 1.f; }
    else if (t == 1) { cJ = 8.f; c0 = 7.f; c1 = 8.f; c2 = 8.f; }
    else             { cJ = 8.f; c0 = 8.f; c1 = 8.f; c2 = 8.f; }

    const size_t ds = (size_t)Bb * Nn * Dd;
    const size_t base0 = ((((size_t)x * 3 + 0) * Bb + b) * Nn + t) * Dd;
    const int c = threadIdx.x * 4;

    float2 G0a = __half22float2(*(const __half2*)&g_G[base0 + c]);
    float2 G0b = __half22float2(*(const __half2*)&g_G[base0 + c + 2]);
    float2 G1a = __half22float2(*(const __half2*)&g_G[base0 + ds + c]);
    float2 G1b = __half22float2(*(const __half2*)&g_G[base0 + ds + c + 2]);
    float2 G2a = __half22float2(*(const __half2*)&g_G[base0 + 2 * ds + c]);
    float2 G2b = __half22float2(*(const __half2*)&g_G[base0 + 2 * ds + c + 2]);
    float4 w0 = *(const float4*)&wc[c];
    float4 w1 = *(const float4*)&wc[Dd + c];
    float4 w2 = *(const float4*)&wc[2 * Dd + c];
    float4 bdv = *(const float4*)&bd[c];
    float4 bcv4 = *(const float4*)&bc[c];

    float G0[4] = {G0a.x, G0a.y, G0b.x, G0b.y};
    float G1[4] = {G1a.x, G1a.y, G1b.x, G1b.y};
    float G2[4] = {G2a.x, G2a.y, G2b.x, G2b.y};
    float wv0[4] = {w0.x, w0.y, w0.z, w0.w};
    float wv1[4] = {w1.x, w1.y, w1.z, w1.w};
    float wv2[4] = {w2.x, w2.y, w2.z, w2.w};
    float bdc[4] = {bdv.x, bdv.y, bdv.z, bdv.w};
    float bcc[4] = {bcv4.x, bcv4.y, bcv4.z, bcv4.w};

    float out[4];
    #pragma unroll
    for (int j = 0; j < 4; j++) {
        float val = cJ * bcc[j] + scale * (wv0[j] * (G0[j] + c0 * bdc[j]) +
                                           wv1[j] * (G1[j] + c1 * bdc[j]) +
                                           wv2[j] * (G2[j] + c2 * bdc[j]));
        out[j] = val * 0.125f;
    }
    int h = c >> 6, dd = c & 63;
    *(float4*)&g_pool[((((size_t)x * Bb + b) * Hh + h) * Nn + t) * DDd + dd] =
        make_float4(out[0], out[1], out[2], out[3]);
}

// ---------------------------------------------------------------------------
// Attention partial v5 (tensor-core, S overlaid on K tiles -> 55.3KB smem,
// 4 CTAs/SM): grid (10 pairs, 64 bh), 128 thr (4 warps).
// ---------------------------------------------------------------------------
#define TS 144                      // tile row stride in bytes (64 halfs + pad)
#define OFF_QH 0
#define OFF_QL (64 * TS)
#define OFF_KH (2 * 64 * TS)
#define OFF_KL (3 * 64 * TS)
#define OFF_VH (4 * 64 * TS)
#define OFF_VL (5 * 64 * TS)
#define OFF_S  OFF_KH               // S (64x68 floats) overlays K tiles
#define ATTN_SMEM (6 * 64 * TS)
#define OFF_PH OFF_QH               // P reuses Q tiles
#define OFF_PL OFF_QL

__global__ void __launch_bounds__(128, 4) attn_partial() {
    extern __shared__ char dsm[];
    const uint32_t sb = smem_u32(dsm);
    float* sS = (float*)(dsm + OFF_S);
    const int qt = c_qt[blockIdx.x];
    const int kc = c_kc[blockIdx.x];
    const int bh = blockIdx.y;
    const int tid = threadIdx.x;
    const int wid = tid >> 5, lane = tid & 31;
    const float* qp = g_pool + ((size_t)0 * Bb * Hh + bh) * Nn * DDd + (size_t)qt * 64 * DDd;
    const float* kp = g_pool + ((size_t)1 * Bb * Hh + bh) * Nn * DDd + (size_t)kc * 64 * DDd;
    const float* vp = g_pool + ((size_t)2 * Bb * Hh + bh) * Nn * DDd + (size_t)kc * 64 * DDd;

    // ---- load + split Q, K (natural layout) and V (transposed) ----
    for (int it = 0; it < 8; it++) {
        int idx = tid + it * 128;
        int row = idx >> 4, f4 = idx & 15;
        float4 qv = *(const float4*)(qp + (size_t)row * 64 + f4 * 4);
        float4 kv = *(const float4*)(kp + (size_t)row * 64 + f4 * 4);
        float4 vv = *(const float4*)(vp + (size_t)row * 64 + f4 * 4);
        float qa[4] = {qv.x, qv.y, qv.z, qv.w};
        float ka[4] = {kv.x, kv.y, kv.z, kv.w};
        float va[4] = {vv.x, vv.y, vv.z, vv.w};
        __half qh[4], ql[4], kh[4], kl[4];
        #pragma unroll
        for (int j = 0; j < 4; j++) {
            qh[j] = __float2half_rn(qa[j]); ql[j] = __float2half_rn(qa[j] - __half2float(qh[j]));
            kh[j] = __float2half_rn(ka[j]); kl[j] = __float2half_rn(ka[j] - __half2float(kh[j]));
        }
        char* bq_ = dsm + OFF_QH + row * TS + f4 * 8;
        char* bql = dsm + OFF_QL + row * TS + f4 * 8;
        char* bk_ = dsm + OFF_KH + row * TS + f4 * 8;
        char* bkl = dsm + OFF_KL + row * TS + f4 * 8;
        ((__half2*)bq_)[0] = __halves2half2(qh[0], qh[1]);
        ((__half2*)bq_)[1] = __halves2half2(qh[2], qh[3]);
        ((__half2*)bql)[0] = __halves2half2(ql[0], ql[1]);
        ((__half2*)bql)[1] = __halves2half2(ql[2], ql[3]);
        ((__half2*)bk_)[0] = __halves2half2(kh[0], kh[1]);
        ((__half2*)bk_)[1] = __halves2half2(kh[2], kh[3]);
        ((__half2*)bkl)[0] = __halves2half2(kl[0], kl[1]);
        ((__half2*)bkl)[1] = __halves2half2(kl[2], kl[3]);
        #pragma unroll
        for (int j = 0; j < 4; j++) {
            int dd = f4 * 4 + j;
            __half vh = __float2half_rn(va[j]);
            __half vl = __float2half_rn(va[j] - __half2float(vh));
            *(__half*)(dsm + OFF_VH + dd * TS + row * 2) = vh;
            *(__half*)(dsm + OFF_VL + dd * TS + row * 2) = vl;
        }
    }
    __syncthreads();

    // ---- S = Q @ K^T (3-term split mma). Warp w -> S rows [w*16, w*16+16).
    const uint32_t aOff = (uint32_t)((wid * 16 + (lane & 15)) * TS + (lane >> 4) * 16);
    const uint32_t bOff = (uint32_t)((((lane >> 4) & 1) * 8 + (lane & 7)) * TS + ((lane >> 3) & 1) * 16);
    {
        float acc[8][4];
        #pragma unroll
        for (int ni = 0; ni < 8; ni++)
            #pragma unroll
            for (int j = 0; j < 4; j++) acc[ni][j] = 0.f;

        const uint32_t aBase[3] = {sb + OFF_QH, sb + OFF_QH, sb + OFF_QL};
        const uint32_t bBase[3] = {sb + OFF_KH, sb + OFF_KL, sb + OFF_KH};
        #pragma unroll
        for (int t = 0; t < 3; t++) {
            #pragma unroll
            for (int kk = 0; kk < 4; kk++) {
                uint32_t ah[4];
                ldsm_x4(ah, aBase[t] + aOff + kk * 32);
                #pragma unroll
                for (int p = 0; p < 4; p++) {
                    uint32_t b4[4];
                    ldsm_x4(b4, bBase[t] + bOff + p * 16 * TS + kk * 32);
                    mma_f16(acc[2 * p],     ah, b4);
                    mma_f16(acc[2 * p + 1], ah, b4 + 2);
                }
            }
        }
        __syncthreads();   // all warps done reading K before S overlays it
        const int r0 = wid * 16 + (lane >> 2);
        const int cb = (lane & 3) * 2;
        #pragma unroll
        for (int ni = 0; ni < 8; ni++) {
            int c = ni * 8 + cb;
            *(float2*)&sS[r0 * 68 + c] = make_float2(acc[ni][0], acc[ni][1]);
            *(float2*)&sS[(r0 + 8) * 68 + c] = make_float2(acc[ni][2], acc[ni][3]);
        }
    }
    __syncthreads();

    // ---- softmax partials: 2 threads/query ----
    {
        const int qq = tid >> 1;
        const int mh = (tid & 1) * 32;
        const int qi = qt * 64 + qq;
        const int lim = qi - kc * 64;
        float mx = -1e30f;
        for (int m = mh; m < mh + 32; m++) {
            if (m <= lim) {
                float s = sS[qq * 68 + m];
                if (s > mx) mx = s;
            }
        }
        float om = __shfl_xor_sync(0xffffffffu, mx, 1);
        if (om > mx) mx = om;
        float li = 0.f;
        for (int m = mh; m < mh + 32; m++) {
            float p = 0.f;
            if (m <= lim) p = __expf(sS[qq * 68 + m] - mx);
            li += p;
            __half ph = __float2half_rn(p);
            *(__half*)(dsm + OFF_PH + qq * TS + m * 2) = ph;
            *(__half*)(dsm + OFF_PL + qq * TS + m * 2) = __float2half_rn(p - __half2float(ph));
        }
        li += __shfl_xor_sync(0xffffffffu, li, 1);
        if ((tid & 1) == 0) {
            const size_t pb = ((size_t)bh * Nn + qi) * 4 + kc;
            g_pm[pb] = mx;
            g_pl[pb] = li;
        }
    }
    __syncthreads();

    // ---- O = P @ Vt (3-term split mma) ----
    {
        float acc[8][4];
        #pragma unroll
        for (int ni = 0; ni < 8; ni++)
            #pragma unroll
            for (int j = 0; j < 4; j++) acc[ni][j] = 0.f;

        const uint32_t aBase[3] = {sb + OFF_PH, sb + OFF_PH, sb + OFF_PL};
        const uint32_t bBase[3] = {sb + OFF_VH, sb + OFF_VL, sb + OFF_VH};
        #pragma unroll
        for (int t = 0; t < 3; t++) {
            #pragma unroll
            for (int kk = 0; kk < 4; kk++) {
                uint32_t ah[4];
                ldsm_x4(ah, aBase[t] + aOff + kk * 32);
                #pragma unroll
                for (int p = 0; p < 4; p++) {
                    uint32_t b4[4];
                    ldsm_x4(b4, bBase[t] + bOff + p * 16 * TS + kk * 32);
                    mma_f16(acc[2 * p],     ah, b4);
                    mma_f16(acc[2 * p + 1], ah, b4 + 2);
                }
            }
        }
        const int r0 = wid * 16 + (lane >> 2);
        const int cb = (lane & 3) * 2;
        const size_t pb0 = ((size_t)bh * Nn + qt * 64 + r0) * 4 + kc;
        const size_t pb1 = ((size_t)bh * Nn + qt * 64 + r0 + 8) * 4 + kc;
        #pragma unroll
        for (int ni = 0; ni < 8; ni++) {
            int dd = ni * 8 + cb;
            *(float2*)&g_pacc[pb0 * 64 + dd] = make_float2(acc[ni][0], acc[ni][1]);
            *(float2*)&g_pacc[pb1 * 64 + dd] = make_float2(acc[ni][2], acc[ni][3]);
        }
    }
}

// ---------------------------------------------------------------------------
// Attention reduce: merge <=4 partials per query, write fp16 merged layout.
// ---------------------------------------------------------------------------
__global__ void __launch_bounds__(128) attn_reduce() {
    const int qt = blockIdx.x;
    const int bh = blockIdx.y;
    const int b = bh >> 4, h = bh & 15;
    const int tid = threadIdx.x;
    const int qi = qt * 64 + (tid >> 1);
    const int hf = (tid & 1) * 32;
    const int np = qt + 1;

    const size_t base = ((size_t)bh * Nn + qi) * 4;
    float M = -1e30f;
    for (int kk = 0; kk < np; kk++) {
        float m = g_pm[base + kk];
        if (m > M) M = m;
    }
    float w[4], L = 0.f;
    for (int kk = 0; kk < np; kk++) {
        w[kk] = __expf(g_pm[base + kk] - M);
        L += g_pl[base + kk] * w[kk];
    }
    float out[32];
    #pragma unroll
    for (int d = 0; d < 32; d++) out[d] = 0.f;
    for (int kk = 0; kk < np; kk++) {
        const float* pa = g_pacc + (base + kk) * 64 + hf;
        float ww = w[kk];
        #pragma unroll
        for (int d = 0; d < 32; d++) out[d] += ww * pa[d];
    }
    float inv = 1.0f / L;
    __half2* outp = (__half2*)(g_OP + ((size_t)(b * Nn + qi)) * Dd + h * 64 + hf);
    #pragma unroll
    for (int d = 0; d < 32; d += 2)
        outp[d >> 1] = __floats2half2_rn(out[d] * inv, out[d + 1] * inv);
}

// ---------------------------------------------------------------------------
extern "C" void kernel_launch(void* const* d_in, const int* in_sizes, int n_in,
                              void* d_out, int out_size) {
    const float* q   = (const float*)d_in[0];
    const float* k   = (const float*)d_in[1];
    const float* v   = (const float*)d_in[2];
    const float* Wq  = (const float*)d_in[3];
    const float* bq  = (const float*)d_in[4];
    const float* Wk  = (const float*)d_in[5];
    const float* bk  = (const float*)d_in[6];
    const float* Wv  = (const float*)d_in[7];
    const float* bv  = (const float*)d_in[8];
    const float* Wup = (const float*)d_in[9];
    const float* bup = (const float*)d_in[10];
    const float* Wc  = (const float*)d_in[11];
    const float* bc  = (const float*)d_in[12];
    const float* wcq = (const float*)d_in[13];
    const float* bcq = (const float*)d_in[14];
    const float* wck = (const float*)d_in[15];
    const float* bck = (const float*)d_in[16];
    const float* wcv = (const float*)d_in[17];
    const float* bcv = (const float*)d_in[18];

    __half *pU, *pWh, *pOP, *pG;
    float *pBias2;
    cudaGetSymbolAddress((void**)&pU, g_U);
    cudaGetSymbolAddress((void**)&pWh, g_Wh);
    cudaGetSymbolAddress((void**)&pOP, g_OP);
    cudaGetSymbolAddress((void**)&pG, g_G);
    cudaGetSymbolAddress((void**)&pBias2, g_bias2);

    const int SM2 = 3 * (128 * 80 + 128 * 80);
    const int SM1 = 3 * (64 * 80 + 128 * 80);
    cudaFuncSetAttribute((const void*)gemm_tc<2, 0>, cudaFuncAttributeMaxDynamicSharedMemorySize, SM2);
    cudaFuncSetAttribute((const void*)gemm_tc<1, 1>, cudaFuncAttributeMaxDynamicSharedMemorySize, SM1);
    cudaFuncSetAttribute((const void*)attn_partial, cudaFuncAttributeMaxDynamicSharedMemorySize, ATTN_SMEM);

    // 1. All preprocessing
    prep_kernel<<<dim3(32, 32, 7), 256>>>(q, k, v, Wq, Wk, Wv, Wup, Wc, bup, bc);

    // 2. Fused projection GEMMs
    const size_t wstep = (size_t)1024 * 1024;
    gemm_tc<2, 0><<<dim3(8, 72), 256, SM2>>>(
        pU, pWh + 0 * wstep, pWh + 1 * wstep, pWh + 2 * wstep,
        pG, nullptr, 24);

    // 3. Combine conv weights/biases/scale -> pooled q/k/v (vectorized)
    combine_kernel<<<dim3(Nn, Bb, 3), 256>>>(wcq, bcq, bq, wck, bck, bk, wcv, bcv, bv);

    // 4. Attention partials (tensor-core, 4 CTAs/SM, ncu capture slot)
    attn_partial<<<dim3(10, Bb * Hh), 128, ATTN_SMEM>>>();

    // 5. Merge partials -> fp16 merged layout
    attn_reduce<<<dim3(4, Bb * Hh), 128>>>();

    // 6. Final dense with folded Wup+Wc (+bias2), broadcast epilogue to d_out
    gemm_tc<1, 1><<<dim3(8, 16), 256, SM1>>>(
        pOP, pWh + 3 * wstep, pWh + 3 * wstep, pWh + 3 * wstep,
        (void*)d_out, pBias2, 16);
}

// round 17
// speedup vs baseline: 1.4477x; 1.0241x over previous
#include <cuda_runtime.h>
#include <cuda_fp16.h>
#include <stdint.h>
#include <math.h>

#define Bb 4
#define Ss 2048
#define Dd 1024
#define Hh 16
#define Nn 256
#define DDd 64

// ---------------- scratch (device globals; no allocation allowed) ----------
__device__ __half g_U[9216 * 1024];          // pooled GEMM A fp16
__device__ __half g_G[9216 * 1024];          // projection GEMM outputs (fp16)
__device__ __half g_Wh[4 * 1024 * 1024];     // fp16 weights [N,K]: Wq,Wk,Wv,W2
__device__ __half g_Phi[3 * 64 * 256 * 64];  // pooled q/k/v hi [x][bh][t][dd]
__device__ __half g_Plo[3 * 64 * 256 * 64];  // pooled q/k/v lo
__device__ __half g_OP[1024 * 1024];         // attn output, merged [b*t][h*64+dd]
__device__ float g_bias2[1024];              // bc + bup_tiled @ Wc
__device__ float g_pm[64 * 256 * 4];         // split-KV partial max
__device__ float g_pl[64 * 256 * 4];         // split-KV partial sum
__device__ float g_pacc[64 * 256 * 4 * 64];  // split-KV partial acc (unnormalized)

__device__ __constant__ int c_qt[10] = {0,1,1,2,2,2,3,3,3,3};
__device__ __constant__ int c_kc[10] = {0,0,1,0,1,2,0,1,2,3};

// ---------------- PTX helpers ----------------------------------------------
static __device__ __forceinline__ uint32_t smem_u32(const void* p) {
    uint32_t r;
    asm("{ .reg .u64 t; cvta.to.shared.u64 t, %1; cvt.u32.u64 %0, t; }" : "=r"(r) : "l"(p));
    return r;
}
static __device__ __forceinline__ void cp16(uint32_t dst, const void* src) {
    asm volatile("cp.async.cg.shared.global [%0], [%1], 16;" :: "r"(dst), "l"(src));
}
#define CP_COMMIT() asm volatile("cp.async.commit_group;" ::: "memory")
#define CP_WAIT1()  asm volatile("cp.async.wait_group 1;" ::: "memory")
#define CP_WAIT0()  asm volatile("cp.async.wait_group 0;" ::: "memory")

static __device__ __forceinline__ void ldsm_x4(uint32_t* r, uint32_t addr) {
    asm volatile("ldmatrix.sync.aligned.m8n8.x4.shared.b16 {%0,%1,%2,%3}, [%4];"
                 : "=r"(r[0]), "=r"(r[1]), "=r"(r[2]), "=r"(r[3]) : "r"(addr));
}
static __device__ __forceinline__ void ldsm_x4t(uint32_t* r, uint32_t addr) {
    asm volatile("ldmatrix.sync.aligned.m8n8.x4.trans.shared.b16 {%0,%1,%2,%3}, [%4];"
                 : "=r"(r[0]), "=r"(r[1]), "=r"(r[2]), "=r"(r[3]) : "r"(addr));
}
static __device__ __forceinline__ void mma_f16(float* c, const uint32_t* a, const uint32_t* b) {
    asm volatile(
        "mma.sync.aligned.m16n8k16.row.col.f32.f16.f16.f32 "
        "{%0,%1,%2,%3}, {%4,%5,%6,%7}, {%8,%9}, {%0,%1,%2,%3};"
        : "+f"(c[0]), "+f"(c[1]), "+f"(c[2]), "+f"(c[3])
        : "r"(a[0]), "r"(a[1]), "r"(a[2]), "r"(a[3]), "r"(b[0]), "r"(b[1]));
}

static __device__ __forceinline__ float4 f4add(float4 a, float4 b) {
    return make_float4(a.x + b.x, a.y + b.y, a.z + b.z, a.w + b.w);
}

// ---------------------------------------------------------------------------
// PREP kernel: all independent preprocessing, dispatched on blockIdx.z.
// ---------------------------------------------------------------------------
#define TSTEP 8
__global__ void __launch_bounds__(256) prep_kernel(
        const float* __restrict__ q, const float* __restrict__ k, const float* __restrict__ v,
        const float* __restrict__ Wq, const float* __restrict__ Wk, const float* __restrict__ Wv,
        const float* __restrict__ Wup, const float* __restrict__ Wc,
        const float* __restrict__ bup, const float* __restrict__ bc) {
    const int z = blockIdx.z;
    const int tid = threadIdx.x;

    if (z < 3) {
        const int b = blockIdx.y;
        if (b >= Bb) return;
        const int tr = blockIdx.x;
        const float* src = (z == 0) ? q : ((z == 1) ? k : v);
        const float4* S = (const float4*)(src + (size_t)b * Ss * Dd);
        const int c4 = tid;
        const int t0 = tr * TSTEP;

        float4 zero = make_float4(0.f, 0.f, 0.f, 0.f);
        int r0 = 8 * t0 - 9, r1 = 8 * t0 - 8;
        float4 prev0 = (r0 >= 0) ? S[(size_t)r0 * 256 + c4] : zero;
        float4 prev1 = (r1 >= 0) ? S[(size_t)r1 * 256 + c4] : zero;

        #pragma unroll
        for (int t = t0; t < t0 + TSTEP; t++) {
            float4 nw[8];
            #pragma unroll
            for (int kk = 0; kk < 8; kk++) {
                int rr = 8 * t - 7 + kk;
                nw[kk] = (rr >= 0) ? S[(size_t)rr * 256 + c4] : zero;
            }
            float4 p6 = f4add(f4add(f4add(nw[0], nw[1]), f4add(nw[2], nw[3])), f4add(nw[4], nw[5]));
            float4 s0 = f4add(f4add(prev0, prev1), p6);
            float4 s1 = f4add(prev1, f4add(p6, nw[6]));
            float4 s2 = f4add(p6, f4add(nw[6], nw[7]));
            float4 sv[3] = {s0, s1, s2};
            #pragma unroll
            for (int d = 0; d < 3; d++) {
                size_t row = (((size_t)(z * 3 + d)) * Bb + b) * Nn + t;
                __half2* dst = (__half2*)g_U + row * 512 + c4 * 2;
                dst[0] = __floats2half2_rn(sv[d].x, sv[d].y);
                dst[1] = __floats2half2_rn(sv[d].z, sv[d].w);
            }
            prev0 = nw[6];
            prev1 = nw[7];
        }
    } else if (z < 6) {
        const float* W = (z == 3) ? Wq : ((z == 4) ? Wk : Wv);
        __half* Oh = g_Wh + (size_t)(z - 3) * 1024 * 1024;
        __shared__ float tile[32][33];
        const int n0 = blockIdx.x * 32, k0 = blockIdx.y * 32;
        const int tx = tid & 31, ty = tid >> 5;
        #pragma unroll
        for (int j = 0; j < 4; j++)
            tile[ty + j * 8][tx] = W[(size_t)(k0 + ty + j * 8) * 1024 + n0 + tx];
        __syncthreads();
        #pragma unroll
        for (int j = 0; j < 4; j++) {
            float val = tile[tx][ty + j * 8];
            Oh[(size_t)(n0 + ty + j * 8) * 1024 + k0 + tx] = __float2half_rn(val);
        }
    } else {
        const int bx = blockIdx.x;
        const int by = blockIdx.y;
        const int h = by >> 1, ddb = (by & 1) * 32;
        __shared__ float sWup[32][65];
        __shared__ float sWc[64][32];
        for (int idx = tid; idx < 32 * 64; idx += 256) {
            int dd = idx >> 6, j = idx & 63;
            sWup[dd][j] = Wup[(size_t)(ddb + dd) * 64 + j];
        }
        for (int idx = tid; idx < 64 * 32; idx += 256) {
            int j = idx >> 5, cl = idx & 31;
            sWc[j][cl] = Wc[(size_t)(h * 64 + j) * 1024 + bx * 32 + cl];
        }
        __syncthreads();
        const int rl = tid & 31;
        const int c0 = (tid >> 5) * 4;
        float o[4] = {0.f, 0.f, 0.f, 0.f};
        #pragma unroll
        for (int j = 0; j < 64; j++) {
            float a = sWup[rl][j];
            o[0] += a * sWc[j][c0 + 0];
            o[1] += a * sWc[j][c0 + 1];
            o[2] += a * sWc[j][c0 + 2];
            o[3] += a * sWc[j][c0 + 3];
        }
        __half* W2t = g_Wh + (size_t)3 * 1024 * 1024;
        const int r = by * 32 + rl;
        #pragma unroll
        for (int i = 0; i < 4; i++)
            W2t[(size_t)(bx * 32 + c0 + i) * 1024 + r] = __float2half_rn(o[i]);
        if (by == 0) {
            __shared__ float red[32][9];
            int col = tid >> 3, part = tid & 7;
            int c = bx * 32 + col;
            float s = 0.f;
            for (int rr = part * 128; rr < part * 128 + 128; rr++)
                s += bup[rr & 63] * Wc[(size_t)rr * 1024 + c];
            red[col][part] = s;
            __syncthreads();
            if (part == 0) {
                float tot = bc[c];
                #pragma unroll
                for (int i = 0; i < 8; i++) tot += red[col][i];
                g_bias2[c] = tot;
            }
        }
    }
}

// ---------------------------------------------------------------------------
// HMMA fp16 GEMM (3-stage, measured-best): C = A @ B^T, fp32 accum.
// ---------------------------------------------------------------------------
#define BROWS 128

template <int MI, int BCAST>
__global__ void __launch_bounds__(256) gemm_tc(
        const __half* __restrict__ A,
        const __half* __restrict__ B0, const __half* __restrict__ B1,
        const __half* __restrict__ B2,
        void* __restrict__ Cv, const float* __restrict__ bias, int mblocks_per_x) {
    constexpr int CTAM = 64 * MI;
    constexpr int ASZ = CTAM * 80;
    constexpr int BSZ = BROWS * 80;
    constexpr int STAGE = ASZ + BSZ;

    extern __shared__ char dsm[];
    const uint32_t sbase = smem_u32(dsm);
    const int tid = threadIdx.x;
    const int wid = tid >> 5, lane = tid & 31;
    const int bn = blockIdx.x, bm = blockIdx.y;
    const int x = bm / mblocks_per_x;
    const __half* Bh = (x == 0) ? B0 : ((x == 1) ? B1 : B2);

    const int warpM = wid >> 1;
    const int warpN = wid & 1;
    const uint32_t aOff = (uint32_t)((warpM * 16 * MI + (lane & 15)) * 80 + (lane >> 4) * 16);
    const uint32_t bOff = (uint32_t)(ASZ +
        (warpN * 64 + ((lane >> 4) & 1) * 8 + (lane & 7)) * 80 + ((lane >> 3) & 1) * 16);

    float acc[MI][8][4];
    #pragma unroll
    for (int mi = 0; mi < MI; mi++)
        #pragma unroll
        for (int ni = 0; ni < 8; ni++)
            #pragma unroll
            for (int j = 0; j < 4; j++) acc[mi][ni][j] = 0.f;

    auto load_chunk = [&](int ch, int st) {
        const uint32_t bb = sbase + st * STAGE;
        const int kof = ch * 32;
        #pragma unroll
        for (int it = 0; it < MI; it++) {
            int idx = tid + it * 256;
            int r = idx >> 2, qq = idx & 3;
            uint32_t dst = bb + r * 80 + qq * 16;
            size_t g = (size_t)(bm * CTAM + r) * 1024 + kof + qq * 8;
            cp16(dst, A + g);
        }
        #pragma unroll
        for (int it = 0; it < 2; it++) {
            int idx = tid + it * 256;
            int r = idx >> 2, qq = idx & 3;
            uint32_t dst = bb + ASZ + r * 80 + qq * 16;
            size_t g = (size_t)(bn * BROWS + r) * 1024 + kof + qq * 8;
            cp16(dst, Bh + g);
        }
        CP_COMMIT();
    };

    load_chunk(0, 0);
    load_chunk(1, 1);

    for (int i = 0; i < 32; i++) {
        CP_WAIT1();
        __syncthreads();
        const uint32_t bb = sbase + (i % 3) * STAGE;
        #pragma unroll
        for (int kk = 0; kk < 2; kk++) {
            uint32_t ah[MI][4];
            #pragma unroll
            for (int mi = 0; mi < MI; mi++)
                ldsm_x4(ah[mi], bb + aOff + mi * 16 * 80 + kk * 32);
            #pragma unroll
            for (int p = 0; p < 4; p++) {
                uint32_t b4[4];
                ldsm_x4(b4, bb + bOff + p * 16 * 80 + kk * 32);
                #pragma unroll
                for (int mi = 0; mi < MI; mi++) {
                    mma_f16(acc[mi][2 * p],     ah[mi], b4);
                    mma_f16(acc[mi][2 * p + 1], ah[mi], b4 + 2);
                }
            }
        }
        if (i + 2 < 32) load_chunk(i + 2, (i + 2) % 3);
        else CP_COMMIT();
    }

    const int row0 = bm * CTAM + warpM * 16 * MI + (lane >> 2);
    const int col0 = bn * 128 + warpN * 64 + (lane & 3) * 2;
    #pragma unroll
    for (int mi = 0; mi < MI; mi++) {
        #pragma unroll
        for (int ni = 0; ni < 8; ni++) {
            int r = row0 + mi * 16;
            int c = col0 + ni * 8;
            if (BCAST) {
                float* C = (float*)Cv;
                float b0 = bias ? bias[c] : 0.f, b1 = bias ? bias[c + 1] : 0.f;
                float2 v0 = make_float2(acc[mi][ni][0] + b0, acc[mi][ni][1] + b1);
                float2 v1 = make_float2(acc[mi][ni][2] + b0, acc[mi][ni][3] + b1);
                int rb = r >> 8, rt = r & 255;
                float* o0 = C + ((size_t)rb * Ss + rt * 8) * 1024 + c;
                int r8 = r + 8;
                int rb2 = r8 >> 8, rt2 = r8 & 255;
                float* o1 = C + ((size_t)rb2 * Ss + rt2 * 8) * 1024 + c;
                #pragma unroll
                for (int rep = 0; rep < 8; rep++) {
                    *(float2*)(o0 + rep * 1024) = v0;
                    *(float2*)(o1 + rep * 1024) = v1;
                }
            } else {
                __half* C = (__half*)Cv;
                *(__half2*)&C[(size_t)r * 1024 + c] =
                    __floats2half2_rn(acc[mi][ni][0], acc[mi][ni][1]);
                *(__half2*)&C[(size_t)(r + 8) * 1024 + c] =
                    __floats2half2_rn(acc[mi][ni][2], acc[mi][ni][3]);
            }
        }
    }
}

// ---------------------------------------------------------------------------
// Combine (vectorized): fold conv weights + biases + norm scale + /8 into
// pooled q/k/v, writing fp16 hi/lo directly (split done once, not per attn CTA).
// ---------------------------------------------------------------------------
__global__ void __launch_bounds__(256) combine_kernel(
        const float* __restrict__ wcq, const float* __restrict__ bcq, const float* __restrict__ bq,
        const float* __restrict__ wck, const float* __restrict__ bck, const float* __restrict__ bk,
        const float* __restrict__ wcv, const float* __restrict__ bcv, const float* __restrict__ bv) {
    const int t = blockIdx.x, b = blockIdx.y, x = blockIdx.z;
    const float* wc = (x == 0) ? wcq : ((x == 1) ? wck : wcv);
    const float* bc = (x == 0) ? bcq : ((x == 1) ? bck : bcv);
    const float* bd = (x == 0) ? bq  : ((x == 1) ? bk  : bv);
    const float scale = (x == 2) ? 1.0f : 0.35355339059327379f;

    float cJ, c0, c1, c2;
    if (t == 0)      { cJ = 1.f; c0 = 0.f; c1 = 0.f; c2 = 1.f; }
    else if (t == 1) { cJ = 8.f; c0 = 7.f; c1 = 8.f; c2 = 8.f; }
    else             { cJ = 8.f; c0 = 8.f; c1 = 8.f; c2 = 8.f; }

    const size_t ds = (size_t)Bb * Nn * Dd;
    const size_t base0 = ((((size_t)x * 3 + 0) * Bb + b) * Nn + t) * Dd;
    const int c = threadIdx.x * 4;

    float2 G0a = __half22float2(*(const __half2*)&g_G[base0 + c]);
    float2 G0b = __half22float2(*(const __half2*)&g_G[base0 + c + 2]);
    float2 G1a = __half22float2(*(const __half2*)&g_G[base0 + ds + c]);
    float2 G1b = __half22float2(*(const __half2*)&g_G[base0 + ds + c + 2]);
    float2 G2a = __half22float2(*(const __half2*)&g_G[base0 + 2 * ds + c]);
    float2 G2b = __half22float2(*(const __half2*)&g_G[base0 + 2 * ds + c + 2]);
    float4 w0 = *(const float4*)&wc[c];
    float4 w1 = *(const float4*)&wc[Dd + c];
    float4 w2 = *(const float4*)&wc[2 * Dd + c];
    float4 bdv = *(const float4*)&bd[c];
    float4 bcv4 = *(const float4*)&bc[c];

    float G0[4] = {G0a.x, G0a.y, G0b.x, G0b.y};
    float G1[4] = {G1a.x, G1a.y, G1b.x, G1b.y};
    float G2[4] = {G2a.x, G2a.y, G2b.x, G2b.y};
    float wv0[4] = {w0.x, w0.y, w0.z, w0.w};
    float wv1[4] = {w1.x, w1.y, w1.z, w1.w};
    float wv2[4] = {w2.x, w2.y, w2.z, w2.w};
    float bdc[4] = {bdv.x, bdv.y, bdv.z, bdv.w};
    float bcc[4] = {bcv4.x, bcv4.y, bcv4.z, bcv4.w};

    __half oh[4], ol[4];
    #pragma unroll
    for (int j = 0; j < 4; j++) {
        float val = cJ * bcc[j] + scale * (wv0[j] * (G0[j] + c0 * bdc[j]) +
                                           wv1[j] * (G1[j] + c1 * bdc[j]) +
                                           wv2[j] * (G2[j] + c2 * bdc[j]));
        val *= 0.125f;
        oh[j] = __float2half_rn(val);
        ol[j] = __float2half_rn(val - __half2float(oh[j]));
    }
    int h = c >> 6, dd = c & 63;
    size_t o = (((size_t)x * Bb + b) * Hh + h) * (Nn * DDd) + (size_t)t * DDd + dd;
    *(__half2*)&g_Phi[o]     = __halves2half2(oh[0], oh[1]);
    *(__half2*)&g_Phi[o + 2] = __halves2half2(oh[2], oh[3]);
    *(__half2*)&g_Plo[o]     = __halves2half2(ol[0], ol[1]);
    *(__half2*)&g_Plo[o + 2] = __halves2half2(ol[2], ol[3]);
}

// ---------------------------------------------------------------------------
// Attention partial v6 (tensor-core, pure cp.async loads, ldmatrix.trans for
// V — no transpose anywhere): grid (10 pairs, 64 bh), 128 thr (4 warps).
// SMEM: 6 tiles of 64 rows x 144B; S (64x68 f32) overlays K after QK mma.
// ---------------------------------------------------------------------------
#define TS 144
#define OFF_QH 0
#define OFF_QL (64 * TS)
#define OFF_KH (2 * 64 * TS)
#define OFF_KL (3 * 64 * TS)
#define OFF_VH (4 * 64 * TS)
#define OFF_VL (5 * 64 * TS)
#define OFF_S  OFF_KH
#define ATTN_SMEM (6 * 64 * TS)
#define OFF_PH OFF_QH
#define OFF_PL OFF_QL

__global__ void __launch_bounds__(128) attn_partial() {
    extern __shared__ char dsm[];
    const uint32_t sb = smem_u32(dsm);
    float* sS = (float*)(dsm + OFF_S);
    const int qt = c_qt[blockIdx.x];
    const int kc = c_kc[blockIdx.x];
    const int bh = blockIdx.y;
    const int tid = threadIdx.x;
    const int wid = tid >> 5, lane = tid & 31;

    // ---- pure cp.async tile loads (fp16 hi/lo precomputed by combine) ----
    {
        const size_t qoff = ((size_t)0 * 64 + bh) * (Nn * DDd) + (size_t)qt * 64 * DDd;
        const size_t koff = ((size_t)1 * 64 + bh) * (Nn * DDd) + (size_t)kc * 64 * DDd;
        const size_t voff = ((size_t)2 * 64 + bh) * (Nn * DDd) + (size_t)kc * 64 * DDd;
        const __half* srcs[6] = {g_Phi + qoff, g_Plo + qoff,
                                 g_Phi + koff, g_Plo + koff,
                                 g_Phi + voff, g_Plo + voff};
        const uint32_t dsts[6] = {OFF_QH, OFF_QL, OFF_KH, OFF_KL, OFF_VH, OFF_VL};
        #pragma unroll
        for (int i = 0; i < 24; i++) {
            const int slot = i >> 2;                 // compile-time per iteration
            int w = (i & 3) * 128 + tid;             // 0..511 within slot
            int row = w >> 3, f4 = w & 7;
            cp16(sb + dsts[slot] + row * TS + f4 * 16,
                 srcs[slot] + (size_t)row * 64 + f4 * 8);
        }
        CP_COMMIT();
        CP_WAIT0();
    }
    __syncthreads();

    // ---- S = Q @ K^T (3-term split mma). Warp w -> S rows [w*16, w*16+16).
    const uint32_t aOff = (uint32_t)((wid * 16 + (lane & 15)) * TS + (lane >> 4) * 16);
    const uint32_t bOff = (uint32_t)((((lane >> 4) & 1) * 8 + (lane & 7)) * TS + ((lane >> 3) & 1) * 16);
    {
        float acc[8][4];
        #pragma unroll
        for (int ni = 0; ni < 8; ni++)
            #pragma unroll
            for (int j = 0; j < 4; j++) acc[ni][j] = 0.f;

        const uint32_t aBase[3] = {sb + OFF_QH, sb + OFF_QH, sb + OFF_QL};
        const uint32_t bBase[3] = {sb + OFF_KH, sb + OFF_KL, sb + OFF_KH};
        #pragma unroll
        for (int t = 0; t < 3; t++) {
            #pragma unroll
            for (int kk = 0; kk < 4; kk++) {
                uint32_t ah[4];
                ldsm_x4(ah, aBase[t] + aOff + kk * 32);
                #pragma unroll
                for (int p = 0; p < 4; p++) {
                    uint32_t b4[4];
                    ldsm_x4(b4, bBase[t] + bOff + p * 16 * TS + kk * 32);
                    mma_f16(acc[2 * p],     ah, b4);
                    mma_f16(acc[2 * p + 1], ah, b4 + 2);
                }
            }
        }
        __syncthreads();   // all warps done reading K before S overlays it
        const int r0 = wid * 16 + (lane >> 2);
        const int cb = (lane & 3) * 2;
        #pragma unroll
        for (int ni = 0; ni < 8; ni++) {
            int c = ni * 8 + cb;
            *(float2*)&sS[r0 * 68 + c] = make_float2(acc[ni][0], acc[ni][1]);
            *(float2*)&sS[(r0 + 8) * 68 + c] = make_float2(acc[ni][2], acc[ni][3]);
        }
    }
    __syncthreads();

    // ---- softmax partials: 2 threads/query (P overlays Q region) ----
    {
        const int qq = tid >> 1;
        const int mh = (tid & 1) * 32;
        const int qi = qt * 64 + qq;
        const int lim = qi - kc * 64;
        float mx = -1e30f;
        for (int m = mh; m < mh + 32; m++) {
            if (m <= lim) {
                float s = sS[qq * 68 + m];
                if (s > mx) mx = s;
            }
        }
        float om = __shfl_xor_sync(0xffffffffu, mx, 1);
        if (om > mx) mx = om;
        float li = 0.f;
        for (int m = mh; m < mh + 32; m++) {
            float p = 0.f;
            if (m <= lim) p = __expf(sS[qq * 68 + m] - mx);
            li += p;
            __half ph = __float2half_rn(p);
            *(__half*)(dsm + OFF_PH + qq * TS + m * 2) = ph;
            *(__half*)(dsm + OFF_PL + qq * TS + m * 2) = __float2half_rn(p - __half2float(ph));
        }
        li += __shfl_xor_sync(0xffffffffu, li, 1);
        if ((tid & 1) == 0) {
            const size_t pb = ((size_t)bh * Nn + qi) * 4 + kc;
            g_pm[pb] = mx;
            g_pl[pb] = li;
        }
    }
    __syncthreads();

    // ---- O = P @ V^T via ldmatrix.trans on natural V (3-term split mma) ----
    {
        float acc[8][4];
        #pragma unroll
        for (int ni = 0; ni < 8; ni++)
            #pragma unroll
            for (int j = 0; j < 4; j++) acc[ni][j] = 0.f;

        // trans B fragment addressing: register r = nh*2+kh from lane group
        // tn = lane>>3: kh = tn&1 (k rows +8), nh = tn>>1 (n cols +8).
        const uint32_t bOffT = (uint32_t)((((lane >> 3) & 1) * 8 + (lane & 7)) * TS + ((lane >> 4) & 1) * 16);
        const uint32_t aBase[3] = {sb + OFF_PH, sb + OFF_PH, sb + OFF_PL};
        const uint32_t bBase[3] = {sb + OFF_VH, sb + OFF_VL, sb + OFF_VH};
        #pragma unroll
        for (int t = 0; t < 3; t++) {
            #pragma unroll
            for (int kk = 0; kk < 4; kk++) {
                uint32_t ah[4];
                ldsm_x4(ah, aBase[t] + aOff + kk * 32);
                #pragma unroll
                for (int p = 0; p < 4; p++) {
                    uint32_t b4[4];
                    ldsm_x4t(b4, bBase[t] + bOffT + kk * 16 * TS + p * 32);
                    mma_f16(acc[2 * p],     ah, b4);
                    mma_f16(acc[2 * p + 1], ah, b4 + 2);
                }
            }
        }
        const int r0 = wid * 16 + (lane >> 2);
        const int cb = (lane & 3) * 2;
        const size_t pb0 = ((size_t)bh * Nn + qt * 64 + r0) * 4 + kc;
        const size_t pb1 = ((size_t)bh * Nn + qt * 64 + r0 + 8) * 4 + kc;
        #pragma unroll
        for (int ni = 0; ni < 8; ni++) {
            int dd = ni * 8 + cb;
            *(float2*)&g_pacc[pb0 * 64 + dd] = make_float2(acc[ni][0], acc[ni][1]);
            *(float2*)&g_pacc[pb1 * 64 + dd] = make_float2(acc[ni][2], acc[ni][3]);
        }
    }
}

// ---------------------------------------------------------------------------
// Attention reduce: merge <=4 partials per query, write fp16 merged layout.
// ---------------------------------------------------------------------------
__global__ void __launch_bounds__(128) attn_reduce() {
    const int qt = blockIdx.x;
    const int bh = blockIdx.y;
    const int b = bh >> 4, h = bh & 15;
    const int tid = threadIdx.x;
    const int qi = qt * 64 + (tid >> 1);
    const int hf = (tid & 1) * 32;
    const int np = qt + 1;

    const size_t base = ((size_t)bh * Nn + qi) * 4;
    float M = -1e30f;
    for (int kk = 0; kk < np; kk++) {
        float m = g_pm[base + kk];
        if (m > M) M = m;
    }
    float w[4], L = 0.f;
    for (int kk = 0; kk < np; kk++) {
        w[kk] = __expf(g_pm[base + kk] - M);
        L += g_pl[base + kk] * w[kk];
    }
    float out[32];
    #pragma unroll
    for (int d = 0; d < 32; d++) out[d] = 0.f;
    for (int kk = 0; kk < np; kk++) {
        const float* pa = g_pacc + (base + kk) * 64 + hf;
        float ww = w[kk];
        #pragma unroll
        for (int d = 0; d < 32; d++) out[d] += ww * pa[d];
    }
    float inv = 1.0f / L;
    __half2* outp = (__half2*)(g_OP + ((size_t)(b * Nn + qi)) * Dd + h * 64 + hf);
    #pragma unroll
    for (int d = 0; d < 32; d += 2)
        outp[d >> 1] = __floats2half2_rn(out[d] * inv, out[d + 1] * inv);
}

// ---------------------------------------------------------------------------
extern "C" void kernel_launch(void* const* d_in, const int* in_sizes, int n_in,
                              void* d_out, int out_size) {
    const float* q   = (const float*)d_in[0];
    const float* k   = (const float*)d_in[1];
    const float* v   = (const float*)d_in[2];
    const float* Wq  = (const float*)d_in[3];
    const float* bq  = (const float*)d_in[4];
    const float* Wk  = (const float*)d_in[5];
    const float* bk  = (const float*)d_in[6];
    const float* Wv  = (const float*)d_in[7];
    const float* bv  = (const float*)d_in[8];
    const float* Wup = (const float*)d_in[9];
    const float* bup = (const float*)d_in[10];
    const float* Wc  = (const float*)d_in[11];
    const float* bc  = (const float*)d_in[12];
    const float* wcq = (const float*)d_in[13];
    const float* bcq = (const float*)d_in[14];
    const float* wck = (const float*)d_in[15];
    const float* bck = (const float*)d_in[16];
    const float* wcv = (const float*)d_in[17];
    const float* bcv = (const float*)d_in[18];

    __half *pU, *pWh, *pOP, *pG;
    float *pBias2;
    cudaGetSymbolAddress((void**)&pU, g_U);
    cudaGetSymbolAddress((void**)&pWh, g_Wh);
    cudaGetSymbolAddress((void**)&pOP, g_OP);
    cudaGetSymbolAddress((void**)&pG, g_G);
    cudaGetSymbolAddress((void**)&pBias2, g_bias2);

    const int SM2 = 3 * (128 * 80 + 128 * 80);
    const int SM1 = 3 * (64 * 80 + 128 * 80);
    cudaFuncSetAttribute((const void*)gemm_tc<2, 0>, cudaFuncAttributeMaxDynamicSharedMemorySize, SM2);
    cudaFuncSetAttribute((const void*)gemm_tc<1, 1>, cudaFuncAttributeMaxDynamicSharedMemorySize, SM1);
    cudaFuncSetAttribute((const void*)attn_partial, cudaFuncAttributeMaxDynamicSharedMemorySize, ATTN_SMEM);

    // 1. All preprocessing
    prep_kernel<<<dim3(32, 32, 7), 256>>>(q, k, v, Wq, Wk, Wv, Wup, Wc, bup, bc);

    // 2. Fused projection GEMMs
    const size_t wstep = (size_t)1024 * 1024;
    gemm_tc<2, 0><<<dim3(8, 72), 256, SM2>>>(
        pU, pWh + 0 * wstep, pWh + 1 * wstep, pWh + 2 * wstep,
        pG, nullptr, 24);

    // 3. Combine -> fp16 hi/lo pooled q/k/v
    combine_kernel<<<dim3(Nn, Bb, 3), 256>>>(wcq, bcq, bq, wck, bck, bk, wcv, bcv, bv);

    // 4. Attention partials (tensor-core, cp.async + ldsm.trans, ncu slot)
    attn_partial<<<dim3(10, Bb * Hh), 128, ATTN_SMEM>>>();

    // 5. Merge partials -> fp16 merged layout
    attn_reduce<<<dim3(4, Bb * Hh), 128>>>();

    // 6. Final dense with folded Wup+Wc (+bias2), broadcast epilogue to d_out
    gemm_tc<1, 1><<<dim3(8, 16), 256, SM1>>>(
        pOP, pWh + 3 * wstep, pWh + 3 * wstep, pWh + 3 * wstep,
        (void*)d_out, pBias2, 16);
}